// round 10
// baseline (speedup 1.0000x reference)
#include <cuda_runtime.h>
#include <cuda_bf16.h>
#include <math.h>
#include <stdint.h>

#define T_ 2048
#define B_ 2
#define E_ 1024
#define H_ 16
#define S_ 64
#define BH_ (B_*H_)
#define LOG2E_ 1.4426950408889634f

// Scratch (static device globals; allocation-free per harness rules)
__device__ __nv_bfloat16 g_qhi[B_*H_*T_*S_];   // [bh][t][d] q hi
__device__ __nv_bfloat16 g_qlo[B_*H_*T_*S_];
__device__ __nv_bfloat16 g_khi[B_*H_*T_*S_];   // [bh][r][d] k2 = (k/32 + Er)*log2e
__device__ __nv_bfloat16 g_klo[B_*H_*T_*S_];
__device__ __nv_bfloat16 g_vhi[B_*H_*T_*S_];   // [bh][r][d]
__device__ __nv_bfloat16 g_vlo[B_*H_*T_*S_];
__device__ __nv_bfloat16 g_zhi[B_*E_*T_];      // Z (proj input) hi, flat [4096][1024]
__device__ __nv_bfloat16 g_zlo[B_*E_*T_];
__device__ __nv_bfloat16 g_whi[E_*E_];         // Wr hi
__device__ __nv_bfloat16 g_wlo[E_*E_];

// ===========================================================================
// mma.sync / ldmatrix / cp.async helpers
// ===========================================================================
__device__ __forceinline__ uint32_t smem_u32(const void* p) {
    uint32_t a;
    asm("{ .reg .u64 t; cvta.to.shared.u64 t, %1; cvt.u32.u64 %0, t; }"
        : "=r"(a) : "l"(p));
    return a;
}
__device__ __forceinline__ void ldsm4(uint32_t* r, uint32_t addr) {
    asm volatile("ldmatrix.sync.aligned.m8n8.x4.shared.b16 {%0,%1,%2,%3}, [%4];"
                 : "=r"(r[0]), "=r"(r[1]), "=r"(r[2]), "=r"(r[3]) : "r"(addr));
}
__device__ __forceinline__ void ldsm4t(uint32_t* r, uint32_t addr) {
    asm volatile("ldmatrix.sync.aligned.m8n8.x4.trans.shared.b16 {%0,%1,%2,%3}, [%4];"
                 : "=r"(r[0]), "=r"(r[1]), "=r"(r[2]), "=r"(r[3]) : "r"(addr));
}
__device__ __forceinline__ void mma_bf16(float* c, const uint32_t* a, const uint32_t* b) {
    asm volatile(
        "mma.sync.aligned.m16n8k16.row.col.f32.bf16.bf16.f32 "
        "{%0,%1,%2,%3}, {%4,%5,%6,%7}, {%8,%9}, {%0,%1,%2,%3};"
        : "+f"(c[0]), "+f"(c[1]), "+f"(c[2]), "+f"(c[3])
        : "r"(a[0]), "r"(a[1]), "r"(a[2]), "r"(a[3]), "r"(b[0]), "r"(b[1]));
}
__device__ __forceinline__ void cpa16(uint32_t dst, const void* src) {
    asm volatile("cp.async.cg.shared.global [%0], [%1], 16;" :: "r"(dst), "l"(src));
}
__device__ __forceinline__ float fexp2(float x) {
    float y; asm("ex2.approx.ftz.f32 %0, %1;" : "=f"(y) : "f"(x)); return y;
}
__device__ __forceinline__ uint32_t pack_bf2(float x, float y) {
    __nv_bfloat16 hx = __float2bfloat16(x), hy = __float2bfloat16(y);
    return (uint32_t)__bfloat16_as_ushort(hx) |
           ((uint32_t)__bfloat16_as_ushort(hy) << 16);
}
// split two floats -> hi-packed u32 + lo-packed u32
__device__ __forceinline__ void split2(float a, float b, uint32_t& hi, uint32_t& lo) {
    __nv_bfloat16 h0 = __float2bfloat16(a), h1 = __float2bfloat16(b);
    hi = (uint32_t)__bfloat16_as_ushort(h0) | ((uint32_t)__bfloat16_as_ushort(h1) << 16);
    lo = pack_bf2(a - __bfloat162float(h0), b - __bfloat162float(h1));
}

// ---------------------------------------------------------------------------
// Kernel 1: QKV projections on mma.sync (3-term bf16 split).
// grid (T/128, H, B), 256 threads (8 warps, warp tile m16 x n64).
// smem: xh 0 (128x144B=18432), xl 18432, then per w in {q,k,v}:
//   Wh at 36864 + w*18432, Wl at +9216.  Total 92160 B.
// ---------------------------------------------------------------------------
__global__ __launch_bounds__(256) void qkv_mma_kernel(
    const float* __restrict__ x,   // [T,B,E]
    const float* __restrict__ Wq,  // [H,S,S]
    const float* __restrict__ Wk,
    const float* __restrict__ Wv,
    const float* __restrict__ Er)  // [S,T]
{
    extern __shared__ __align__(16) char qsmem[];
    const uint32_t sb = smem_u32(qsmem);
    const int tid = threadIdx.x, wid = tid >> 5, lane = tid & 31;
    const int h = blockIdx.y, b = blockIdx.z;
    const int t0 = blockIdx.x * 128;

    // ---- load + split x tile [128][64] ----
    {
        const int r  = tid >> 1;
        const int d0 = (tid & 1) * 32;
        #pragma unroll
        for (int q = 0; q < 8; q++) {
            float4 v4 = *(const float4*)&x[(size_t)(t0 + r)*(B_*E_) + b*E_ + h*S_ + d0 + q*4];
            uint32_t h0, l0, h1, l1;
            split2(v4.x, v4.y, h0, l0);
            split2(v4.z, v4.w, h1, l1);
            uint32_t off = (uint32_t)r*144 + (uint32_t)(d0 + q*4)*2;
            *(uint2*)(qsmem + off)          = make_uint2(h0, h1);
            *(uint2*)(qsmem + 18432 + off)  = make_uint2(l0, l1);
        }
    }
    // ---- load + split W tiles [64][64] x 3 ----
    {
        const float* W[3] = { Wq + h*4096, Wk + h*4096, Wv + h*4096 };
        const int dd = tid >> 2;
        const int s0 = (tid & 3) * 16;
        #pragma unroll
        for (int w = 0; w < 3; w++) {
            uint32_t basew = 36864 + (uint32_t)w*18432;
            #pragma unroll
            for (int q = 0; q < 4; q++) {
                float4 w4 = *(const float4*)&W[w][dd*64 + s0 + q*4];
                uint32_t h0, l0, h1, l1;
                split2(w4.x, w4.y, h0, l0);
                split2(w4.z, w4.w, h1, l1);
                uint32_t off = (uint32_t)dd*144 + (uint32_t)(s0 + q*4)*2;
                *(uint2*)(qsmem + basew + off)         = make_uint2(h0, h1);
                *(uint2*)(qsmem + basew + 9216 + off)  = make_uint2(l0, l1);
            }
        }
    }
    __syncthreads();

    // ---- hoist A (x) fragments ----
    const uint32_t aoff = (uint32_t)(wid*16 + (lane & 15))*144 + ((lane >> 4) * 16);
    uint32_t axh[4][4], axl[4][4];
    #pragma unroll
    for (int ks = 0; ks < 4; ks++) {
        ldsm4(axh[ks], sb + aoff + ks*32);
        ldsm4(axl[ks], sb + 18432 + aoff + ks*32);
    }

    const uint32_t koff4 = (uint32_t)((lane & 7) + ((lane >> 4) << 3))*144 + (((lane >> 3) & 1) << 4);
    const size_t base = (size_t)(b*H_ + h) * T_ + t0;
    const int g = lane >> 2, tg = lane & 3;

    #pragma unroll
    for (int w = 0; w < 3; w++) {
        const uint32_t wbh = sb + 36864 + (uint32_t)w*18432;
        float sc[8][4];
        #pragma unroll
        for (int nf = 0; nf < 8; nf++)
            #pragma unroll
            for (int r = 0; r < 4; r++) sc[nf][r] = 0.0f;

        #pragma unroll
        for (int ks = 0; ks < 4; ks++) {
            #pragma unroll
            for (int p = 0; p < 4; p++) {
                uint32_t bh4[4], bl4[4];
                uint32_t ka = wbh + (uint32_t)p*2304 + koff4 + ks*32;
                ldsm4(bh4, ka);
                ldsm4(bl4, ka + 9216);
                mma_bf16(sc[2*p],   axh[ks], bh4);
                mma_bf16(sc[2*p],   axh[ks], bl4);
                mma_bf16(sc[2*p],   axl[ks], bh4);
                mma_bf16(sc[2*p+1], axh[ks], bh4 + 2);
                mma_bf16(sc[2*p+1], axh[ks], bl4 + 2);
                mma_bf16(sc[2*p+1], axl[ks], bh4 + 2);
            }
        }

        // ---- epilogue ----
        __nv_bfloat16* Ghi = (w == 0) ? g_qhi : (w == 1) ? g_khi : g_vhi;
        __nv_bfloat16* Glo = (w == 0) ? g_qlo : (w == 1) ? g_klo : g_vlo;
        #pragma unroll
        for (int nf = 0; nf < 8; nf++) {
            const int col = nf*8 + tg*2;
            #pragma unroll
            for (int h2 = 0; h2 < 2; h2++) {
                const int row = wid*16 + g + h2*8;
                float c0 = sc[nf][2*h2], c1 = sc[nf][2*h2+1];
                if (w == 1) {
                    int t = t0 + row;
                    c0 = (c0*(1.0f/32.0f) + Er[(size_t)col*T_ + t]) * LOG2E_;
                    c1 = (c1*(1.0f/32.0f) + Er[(size_t)(col+1)*T_ + t]) * LOG2E_;
                }
                uint32_t hi, lo;
                split2(c0, c1, hi, lo);
                size_t idx = (base + row)*S_ + col;
                *(uint32_t*)&Ghi[idx] = hi;
                *(uint32_t*)&Glo[idx] = lo;
            }
        }
    }
}

// ---------------------------------------------------------------------------
// Kernel 2: flash attention on mma.sync. BM=128, BN=64, D=64, 8 warps.
// 3-stage cp.async pipeline; Q fragments hoisted; K loaded as ldsm4 n16-pairs.
// smem: Qh 0, Ql 18432, 3 bufs at 36864 + s*36864
//   (buf: Kh +0, Kl +9216, Vh +18432, Vl +27648). Total 147456 B.
// ---------------------------------------------------------------------------
__global__ __launch_bounds__(256) void attn_mma_kernel()
{
    extern __shared__ __align__(16) char asmem[];
    const uint32_t sb = smem_u32(asmem);
    const int tid = threadIdx.x, wid = tid >> 5, lane = tid & 31;
    const int qi = (int)gridDim.x - 1 - (int)blockIdx.x;   // big tiles first
    const int bh = blockIdx.y, t0 = qi * 128;

    const __nv_bfloat16* qh = g_qhi + (size_t)bh*T_*S_;
    const __nv_bfloat16* ql = g_qlo + (size_t)bh*T_*S_;
    const __nv_bfloat16* kh = g_khi + (size_t)bh*T_*S_;
    const __nv_bfloat16* kl = g_klo + (size_t)bh*T_*S_;
    const __nv_bfloat16* vh = g_vhi + (size_t)bh*T_*S_;
    const __nv_bfloat16* vl = g_vlo + (size_t)bh*T_*S_;

    // group 0: Q (hi+lo)
    #pragma unroll
    for (int it = 0; it < 4; it++) {
        int idx = it*256 + tid, row = idx >> 3, ch = idx & 7;
        uint32_t so = (uint32_t)row*144 + ch*16;
        size_t go = (size_t)(t0 + row)*64 + ch*8;
        cpa16(sb + so, qh + go);
        cpa16(sb + 18432 + so, ql + go);
    }
    asm volatile("cp.async.commit_group;" ::: "memory");

#define APREF(jj, bb) do {                                                      \
        uint32_t base_ = sb + 36864 + (uint32_t)(bb)*36864;                     \
        _Pragma("unroll")                                                       \
        for (int it_ = 0; it_ < 2; it_++) {                                     \
            int idx_ = it_*256 + tid, row_ = idx_ >> 3, ch_ = idx_ & 7;         \
            uint32_t so_ = (uint32_t)row_*144 + ch_*16;                         \
            size_t go_ = (size_t)((jj)*64 + row_)*64 + ch_*8;                   \
            cpa16(base_ + so_,         kh + go_);                               \
            cpa16(base_ + 9216  + so_, kl + go_);                               \
            cpa16(base_ + 18432 + so_, vh + go_);                               \
            cpa16(base_ + 27648 + so_, vl + go_);                               \
        }                                                                       \
        asm volatile("cp.async.commit_group;" ::: "memory");                    \
    } while (0)

    const int jmax = 2*qi + 1;
    APREF(0, 0);
    APREF(1, 1);

    // wait for Q (allow the two K/V groups to remain in flight)
    asm volatile("cp.async.wait_group 2;" ::: "memory");
    __syncthreads();

    // hoist Q fragments (loop-invariant)
    const uint32_t qoff = (uint32_t)(wid*16 + (lane & 15))*144 + ((lane >> 4) * 16);
    uint32_t aqh[4][4], aql[4][4];
    #pragma unroll
    for (int ks = 0; ks < 4; ks++) {
        ldsm4(aqh[ks], sb + qoff + ks*32);
        ldsm4(aql[ks], sb + 18432 + qoff + ks*32);
    }

    const uint32_t koff4 = (uint32_t)((lane & 7) + ((lane >> 4) << 3))*144 + (((lane >> 3) & 1) << 4);
    const uint32_t voff = (uint32_t)(((lane >> 3) & 1)*8 + (lane & 7))*144 + ((lane >> 4) * 16);

    float m0 = -1e30f, m1 = -1e30f, l0 = 0.0f, l1 = 0.0f;
    float o[8][4];
    #pragma unroll
    for (int nf = 0; nf < 8; nf++)
        #pragma unroll
        for (int r = 0; r < 4; r++) o[nf][r] = 0.0f;

    for (int j = 0; j <= jmax; j++) {
        if (j < jmax) {
            asm volatile("cp.async.wait_group 1;" ::: "memory");
        } else {
            asm volatile("cp.async.wait_group 0;" ::: "memory");
        }
        __syncthreads();
        if (j + 2 <= jmax) APREF(j + 2, (j + 2) % 3);

        const uint32_t kbb = sb + 36864 + (uint32_t)(j % 3)*36864;
        const uint32_t vbb = kbb + 18432;

        // ---- S = Q @ K2^T (3-term bf16 split; K via n16 ldsm4 pairs) ----
        float sc[8][4];
        #pragma unroll
        for (int nf = 0; nf < 8; nf++)
            #pragma unroll
            for (int r = 0; r < 4; r++) sc[nf][r] = 0.0f;

        #pragma unroll
        for (int ks = 0; ks < 4; ks++) {
            #pragma unroll
            for (int p = 0; p < 4; p++) {
                uint32_t bh4[4], bl4[4];
                uint32_t ka = kbb + (uint32_t)p*2304 + koff4 + ks*32;
                ldsm4(bh4, ka);
                ldsm4(bl4, ka + 9216);
                mma_bf16(sc[2*p],   aqh[ks], bh4);
                mma_bf16(sc[2*p],   aqh[ks], bl4);
                mma_bf16(sc[2*p],   aql[ks], bh4);
                mma_bf16(sc[2*p+1], aqh[ks], bh4 + 2);
                mma_bf16(sc[2*p+1], aqh[ks], bl4 + 2);
                mma_bf16(sc[2*p+1], aql[ks], bh4 + 2);
            }
        }

        // ---- causal mask (diagonal-straddling tiles only) ----
        if (j >= 2*qi) {
            const int rb = t0 + wid*16 + (lane >> 2);
            const int cb = j*64 + (lane & 3)*2;
            #pragma unroll
            for (int nf = 0; nf < 8; nf++) {
                int c = cb + nf*8;
                if (c     > rb)     sc[nf][0] = -1e30f;
                if (c + 1 > rb)     sc[nf][1] = -1e30f;
                if (c     > rb + 8) sc[nf][2] = -1e30f;
                if (c + 1 > rb + 8) sc[nf][3] = -1e30f;
            }
        }

        // ---- online softmax (base-2; log2e folded into k2) ----
        float rm0 = -1e30f, rm1 = -1e30f;
        #pragma unroll
        for (int nf = 0; nf < 8; nf++) {
            rm0 = fmaxf(rm0, fmaxf(sc[nf][0], sc[nf][1]));
            rm1 = fmaxf(rm1, fmaxf(sc[nf][2], sc[nf][3]));
        }
        rm0 = fmaxf(rm0, __shfl_xor_sync(0xffffffffu, rm0, 1));
        rm0 = fmaxf(rm0, __shfl_xor_sync(0xffffffffu, rm0, 2));
        rm1 = fmaxf(rm1, __shfl_xor_sync(0xffffffffu, rm1, 1));
        rm1 = fmaxf(rm1, __shfl_xor_sync(0xffffffffu, rm1, 2));
        float mn0 = fmaxf(m0, rm0), mn1 = fmaxf(m1, rm1);
        float a0 = fexp2(m0 - mn0), a1 = fexp2(m1 - mn1);
        m0 = mn0; m1 = mn1;

        float rs0 = 0.0f, rs1 = 0.0f;
        #pragma unroll
        for (int nf = 0; nf < 8; nf++) {
            sc[nf][0] = fexp2(sc[nf][0] - mn0);
            sc[nf][1] = fexp2(sc[nf][1] - mn0);
            sc[nf][2] = fexp2(sc[nf][2] - mn1);
            sc[nf][3] = fexp2(sc[nf][3] - mn1);
            rs0 += sc[nf][0] + sc[nf][1];
            rs1 += sc[nf][2] + sc[nf][3];
        }
        rs0 += __shfl_xor_sync(0xffffffffu, rs0, 1);
        rs0 += __shfl_xor_sync(0xffffffffu, rs0, 2);
        rs1 += __shfl_xor_sync(0xffffffffu, rs1, 1);
        rs1 += __shfl_xor_sync(0xffffffffu, rs1, 2);
        l0 = l0*a0 + rs0;
        l1 = l1*a1 + rs1;
        #pragma unroll
        for (int nf = 0; nf < 8; nf++) {
            o[nf][0] *= a0; o[nf][1] *= a0;
            o[nf][2] *= a1; o[nf][3] *= a1;
        }

        // ---- pack P fragments (C frag pairs -> A frags), hi/lo split ----
        uint32_t ph[4][4], pl[4][4];
        #pragma unroll
        for (int kb = 0; kb < 4; kb++) {
            const float* s0 = sc[2*kb];
            const float* s1 = sc[2*kb+1];
            float rr[8] = {s0[0], s0[1], s0[2], s0[3], s1[0], s1[1], s1[2], s1[3]};
            #pragma unroll
            for (int q2 = 0; q2 < 4; q2++)
                split2(rr[q2*2], rr[q2*2+1], ph[kb][q2], pl[kb][q2]);
        }

        // ---- O += P @ V (3-term bf16 split; V via ldmatrix.trans) ----
        #pragma unroll
        for (int kb = 0; kb < 4; kb++) {
            #pragma unroll
            for (int np = 0; np < 4; np++) {
                uint32_t v4h[4], v4l[4];
                uint32_t va = vbb + (uint32_t)kb*2304 + voff + np*32;
                ldsm4t(v4h, va);
                ldsm4t(v4l, va + 9216);
                mma_bf16(o[2*np],   ph[kb], v4h);
                mma_bf16(o[2*np],   ph[kb], v4l);
                mma_bf16(o[2*np],   pl[kb], v4h);
                mma_bf16(o[2*np+1], ph[kb], v4h + 2);
                mma_bf16(o[2*np+1], ph[kb], v4l + 2);
                mma_bf16(o[2*np+1], pl[kb], v4h + 2);
            }
        }
    }
    __syncthreads();

    // ---- epilogue: normalize, stage [d][t] in smem, write Z hi/lo e-major ----
    float* stage = (float*)(asmem + 36864);   // [64][132] floats
    {
        float inv0 = 1.0f / l0, inv1 = 1.0f / l1;
        const int g = lane >> 2, tg = lane & 3;
        const int tl = wid*16 + g;
        #pragma unroll
        for (int nf = 0; nf < 8; nf++) {
            int d = nf*8 + tg*2;
            stage[d*132 + tl]           = o[nf][0] * inv0;
            stage[(d+1)*132 + tl]       = o[nf][1] * inv0;
            stage[d*132 + tl + 8]       = o[nf][2] * inv1;
            stage[(d+1)*132 + tl + 8]   = o[nf][3] * inv1;
        }
    }
    __syncthreads();

    const int b = bh >> 4, h = bh & 15;
    const size_t basez = ((size_t)b*E_ + h*S_) * T_;
    #pragma unroll
    for (int it = 0; it < 32; it++) {
        int idx = it*256 + tid;
        int d = idx >> 7, t = idx & 127;
        float y = stage[d*132 + t];
        __nv_bfloat16 hi = __float2bfloat16(y);
        size_t off = basez + (size_t)d*T_ + t0 + t;
        g_zhi[off] = hi;
        g_zlo[off] = __float2bfloat16(y - __bfloat162float(hi));
    }
}

// ---------------------------------------------------------------------------
// Kernel 3a: Wr -> bf16 hi/lo split
// ---------------------------------------------------------------------------
__global__ __launch_bounds__(256) void wconv_kernel(const float* __restrict__ Wr)
{
    size_t i = ((size_t)blockIdx.x*256 + threadIdx.x) * 4;
    float4 w = *(const float4*)&Wr[i];
    float v[4] = {w.x, w.y, w.z, w.w};
    #pragma unroll
    for (int q = 0; q < 4; q++) {
        __nv_bfloat16 hi = __float2bfloat16(v[q]);
        g_whi[i+q] = hi;
        g_wlo[i+q] = __float2bfloat16(v[q] - __bfloat162float(hi));
    }
}

// ---------------------------------------------------------------------------
// Kernel 3b: output projection via mma.sync (bf16, 3-term split).
// B fragments via n16 ldsm4 pairs.
// ---------------------------------------------------------------------------
#define PTILE_ (128*80)
#define PBUF_  (4*PTILE_)
__global__ __launch_bounds__(256) void proj_mma_kernel(
    const float* __restrict__ br, float* __restrict__ out)
{
    extern __shared__ __align__(128) char ps[];
    const uint32_t sb = smem_u32(ps);
    const int tid = threadIdx.x, wid = tid >> 5, lane = tid & 31;
    const int n0 = blockIdx.x * 128, m0 = blockIdx.y * 128;
    const int wm = wid >> 2, wn = wid & 3;

    float acc[4][4][4];
    #pragma unroll
    for (int mf = 0; mf < 4; mf++)
        #pragma unroll
        for (int nf = 0; nf < 4; nf++)
            #pragma unroll
            for (int r = 0; r < 4; r++) acc[mf][nf][r] = 0.0f;

    const int lrow = tid >> 2, lc16 = tid & 3;

    #define ISSUE(cc, bb) do {                                                  \
        const int k0i = (cc) * 32;                                              \
        uint32_t base = sb + (bb) * PBUF_;                                      \
        _Pragma("unroll")                                                       \
        for (int q = 0; q < 2; q++) {                                           \
            int row = lrow + q*64;                                              \
            uint32_t soff = (uint32_t)row*80 + (uint32_t)lc16*16;               \
            size_t ga = (size_t)(m0 + row)*E_ + k0i + lc16*8;                   \
            size_t gb = (size_t)(n0 + row)*E_ + k0i + lc16*8;                   \
            cpa16(base + 0*PTILE_ + soff, g_zhi + ga);                          \
            cpa16(base + 1*PTILE_ + soff, g_zlo + ga);                          \
            cpa16(base + 2*PTILE_ + soff, g_whi + gb);                          \
            cpa16(base + 3*PTILE_ + soff, g_wlo + gb);                          \
        }                                                                       \
        asm volatile("cp.async.commit_group;" ::: "memory");                    \
    } while (0)

    const uint32_t koff4p = (uint32_t)((lane & 7) + ((lane >> 4) << 3))*80 + (((lane >> 3) & 1) << 4);

    ISSUE(0, 0);
    for (int c = 0; c < 32; c++) {
        const int buf = c & 1;
        if (c + 1 < 32) {
            ISSUE(c + 1, buf ^ 1);
            asm volatile("cp.async.wait_group 1;" ::: "memory");
        } else {
            asm volatile("cp.async.wait_group 0;" ::: "memory");
        }
        __syncthreads();

        const uint32_t Ah = sb + buf*PBUF_;
        const uint32_t Al = Ah + PTILE_;
        const uint32_t Bh = Ah + 2*PTILE_;
        const uint32_t Bl = Ah + 3*PTILE_;

        #pragma unroll
        for (int ks = 0; ks < 2; ks++) {
            uint32_t ah[4][4], al[4][4], bh4[2][4], bl4[2][4];
            const uint32_t akoff = (uint32_t)(ks*32 + (lane >> 4)*16);
            const int am = lane & 15;
            #pragma unroll
            for (int mf = 0; mf < 4; mf++) {
                uint32_t ro = (uint32_t)(wm*64 + mf*16 + am)*80 + akoff;
                ldsm4(ah[mf], Ah + ro);
                ldsm4(al[mf], Al + ro);
            }
            #pragma unroll
            for (int p = 0; p < 2; p++) {
                uint32_t ro = (uint32_t)(wn*32 + p*16)*80 + koff4p + ks*32;
                ldsm4(bh4[p], Bh + ro);
                ldsm4(bl4[p], Bl + ro);
            }
            #pragma unroll
            for (int mf = 0; mf < 4; mf++)
                #pragma unroll
                for (int p = 0; p < 2; p++) {
                    mma_bf16(acc[mf][2*p],   ah[mf], bh4[p]);
                    mma_bf16(acc[mf][2*p],   ah[mf], bl4[p]);
                    mma_bf16(acc[mf][2*p],   al[mf], bh4[p]);
                    mma_bf16(acc[mf][2*p+1], ah[mf], bh4[p] + 2);
                    mma_bf16(acc[mf][2*p+1], ah[mf], bl4[p] + 2);
                    mma_bf16(acc[mf][2*p+1], al[mf], bh4[p] + 2);
                }
        }
        __syncthreads();
    }

    const int g = lane >> 2, tg = lane & 3;
    #pragma unroll
    for (int nf = 0; nf < 4; nf++) {
        const int col = n0 + wn*32 + nf*8 + tg*2;
        float2 bb = *(const float2*)&br[col];
        #pragma unroll
        for (int mf = 0; mf < 4; mf++) {
            const int row = m0 + wm*64 + mf*16 + g;
            float2 v0 = make_float2(acc[mf][nf][0] + bb.x, acc[mf][nf][1] + bb.y);
            float2 v1 = make_float2(acc[mf][nf][2] + bb.x, acc[mf][nf][3] + bb.y);
            *(float2*)&out[(size_t)row*E_ + col]       = v0;
            *(float2*)&out[(size_t)(row + 8)*E_ + col] = v1;
        }
    }
}

// ---------------------------------------------------------------------------
extern "C" void kernel_launch(void* const* d_in, const int* in_sizes, int n_in,
                              void* d_out, int out_size)
{
    const float* x  = (const float*)d_in[0];
    const float* Wq = (const float*)d_in[1];
    const float* Wk = (const float*)d_in[2];
    const float* Wv = (const float*)d_in[3];
    const float* Er = (const float*)d_in[4];
    const float* Wr = (const float*)d_in[5];
    const float* br = (const float*)d_in[6];
    float* out = (float*)d_out;

    const int smem_qkv = 92160;
    cudaFuncSetAttribute(qkv_mma_kernel,
                         cudaFuncAttributeMaxDynamicSharedMemorySize, smem_qkv);
    qkv_mma_kernel<<<dim3(T_/128, H_, B_), 256, smem_qkv>>>(x, Wq, Wk, Wv, Er);

    wconv_kernel<<<(E_*E_)/(256*4), 256>>>(Wr);

    const int smem_attn = 147456;
    cudaFuncSetAttribute(attn_mma_kernel,
                         cudaFuncAttributeMaxDynamicSharedMemorySize, smem_attn);
    attn_mma_kernel<<<dim3(T_/128, BH_), 256, smem_attn>>>();

    const int smem_proj = 2 * PBUF_;  // 81920
    cudaFuncSetAttribute(proj_mma_kernel,
                         cudaFuncAttributeMaxDynamicSharedMemorySize, smem_proj);
    proj_mma_kernel<<<dim3(E_/128, (B_*T_)/128), 256, smem_proj>>>(br, out);
}

// round 11
// speedup vs baseline: 1.0273x; 1.0273x over previous
#include <cuda_runtime.h>
#include <cuda_bf16.h>
#include <math.h>
#include <stdint.h>

#define T_ 2048
#define B_ 2
#define E_ 1024
#define H_ 16
#define S_ 64
#define BH_ (B_*H_)
#define LOG2E_ 1.4426950408889634f

// Scratch (static device globals; allocation-free per harness rules)
__device__ __nv_bfloat16 g_qhi[B_*H_*T_*S_];   // [bh][t][d] q hi
__device__ __nv_bfloat16 g_qlo[B_*H_*T_*S_];
__device__ __nv_bfloat16 g_khi[B_*H_*T_*S_];   // [bh][r][d] k2 = (k/32 + Er)*log2e
__device__ __nv_bfloat16 g_klo[B_*H_*T_*S_];
__device__ __nv_bfloat16 g_vhi[B_*H_*T_*S_];   // [bh][r][d]
__device__ __nv_bfloat16 g_vlo[B_*H_*T_*S_];
__device__ __nv_bfloat16 g_zhi[B_*E_*T_];      // Z (proj input) hi, flat [4096][1024]
__device__ __nv_bfloat16 g_zlo[B_*E_*T_];
__device__ __nv_bfloat16 g_whi[E_*E_];         // Wr hi
__device__ __nv_bfloat16 g_wlo[E_*E_];

// ===========================================================================
// mma.sync / ldmatrix / cp.async helpers
// ===========================================================================
__device__ __forceinline__ uint32_t smem_u32(const void* p) {
    uint32_t a;
    asm("{ .reg .u64 t; cvta.to.shared.u64 t, %1; cvt.u32.u64 %0, t; }"
        : "=r"(a) : "l"(p));
    return a;
}
__device__ __forceinline__ void ldsm4(uint32_t* r, uint32_t addr) {
    asm volatile("ldmatrix.sync.aligned.m8n8.x4.shared.b16 {%0,%1,%2,%3}, [%4];"
                 : "=r"(r[0]), "=r"(r[1]), "=r"(r[2]), "=r"(r[3]) : "r"(addr));
}
__device__ __forceinline__ void ldsm4t(uint32_t* r, uint32_t addr) {
    asm volatile("ldmatrix.sync.aligned.m8n8.x4.trans.shared.b16 {%0,%1,%2,%3}, [%4];"
                 : "=r"(r[0]), "=r"(r[1]), "=r"(r[2]), "=r"(r[3]) : "r"(addr));
}
__device__ __forceinline__ void mma_bf16(float* c, const uint32_t* a, const uint32_t* b) {
    asm volatile(
        "mma.sync.aligned.m16n8k16.row.col.f32.bf16.bf16.f32 "
        "{%0,%1,%2,%3}, {%4,%5,%6,%7}, {%8,%9}, {%0,%1,%2,%3};"
        : "+f"(c[0]), "+f"(c[1]), "+f"(c[2]), "+f"(c[3])
        : "r"(a[0]), "r"(a[1]), "r"(a[2]), "r"(a[3]), "r"(b[0]), "r"(b[1]));
}
__device__ __forceinline__ void cpa16(uint32_t dst, const void* src) {
    asm volatile("cp.async.cg.shared.global [%0], [%1], 16;" :: "r"(dst), "l"(src));
}
__device__ __forceinline__ float fexp2(float x) {
    float y; asm("ex2.approx.ftz.f32 %0, %1;" : "=f"(y) : "f"(x)); return y;
}
__device__ __forceinline__ uint32_t pack_bf2(float x, float y) {
    __nv_bfloat16 hx = __float2bfloat16(x), hy = __float2bfloat16(y);
    return (uint32_t)__bfloat16_as_ushort(hx) |
           ((uint32_t)__bfloat16_as_ushort(hy) << 16);
}
// split two floats -> hi-packed u32 + lo-packed u32
__device__ __forceinline__ void split2(float a, float b, uint32_t& hi, uint32_t& lo) {
    __nv_bfloat16 h0 = __float2bfloat16(a), h1 = __float2bfloat16(b);
    hi = (uint32_t)__bfloat16_as_ushort(h0) | ((uint32_t)__bfloat16_as_ushort(h1) << 16);
    lo = pack_bf2(a - __bfloat162float(h0), b - __bfloat162float(h1));
}

// ---------------------------------------------------------------------------
// Kernel 1: QKV projections on mma.sync (3-term bf16 split). Unchanged.
// ---------------------------------------------------------------------------
__global__ __launch_bounds__(256) void qkv_mma_kernel(
    const float* __restrict__ x,   // [T,B,E]
    const float* __restrict__ Wq,  // [H,S,S]
    const float* __restrict__ Wk,
    const float* __restrict__ Wv,
    const float* __restrict__ Er)  // [S,T]
{
    extern __shared__ __align__(16) char qsmem[];
    const uint32_t sb = smem_u32(qsmem);
    const int tid = threadIdx.x, wid = tid >> 5, lane = tid & 31;
    const int h = blockIdx.y, b = blockIdx.z;
    const int t0 = blockIdx.x * 128;

    // ---- load + split x tile [128][64] ----
    {
        const int r  = tid >> 1;
        const int d0 = (tid & 1) * 32;
        #pragma unroll
        for (int q = 0; q < 8; q++) {
            float4 v4 = *(const float4*)&x[(size_t)(t0 + r)*(B_*E_) + b*E_ + h*S_ + d0 + q*4];
            uint32_t h0, l0, h1, l1;
            split2(v4.x, v4.y, h0, l0);
            split2(v4.z, v4.w, h1, l1);
            uint32_t off = (uint32_t)r*144 + (uint32_t)(d0 + q*4)*2;
            *(uint2*)(qsmem + off)          = make_uint2(h0, h1);
            *(uint2*)(qsmem + 18432 + off)  = make_uint2(l0, l1);
        }
    }
    // ---- load + split W tiles [64][64] x 3 ----
    {
        const float* W[3] = { Wq + h*4096, Wk + h*4096, Wv + h*4096 };
        const int dd = tid >> 2;
        const int s0 = (tid & 3) * 16;
        #pragma unroll
        for (int w = 0; w < 3; w++) {
            uint32_t basew = 36864 + (uint32_t)w*18432;
            #pragma unroll
            for (int q = 0; q < 4; q++) {
                float4 w4 = *(const float4*)&W[w][dd*64 + s0 + q*4];
                uint32_t h0, l0, h1, l1;
                split2(w4.x, w4.y, h0, l0);
                split2(w4.z, w4.w, h1, l1);
                uint32_t off = (uint32_t)dd*144 + (uint32_t)(s0 + q*4)*2;
                *(uint2*)(qsmem + basew + off)         = make_uint2(h0, h1);
                *(uint2*)(qsmem + basew + 9216 + off)  = make_uint2(l0, l1);
            }
        }
    }
    __syncthreads();

    // ---- hoist A (x) fragments ----
    const uint32_t aoff = (uint32_t)(wid*16 + (lane & 15))*144 + ((lane >> 4) * 16);
    uint32_t axh[4][4], axl[4][4];
    #pragma unroll
    for (int ks = 0; ks < 4; ks++) {
        ldsm4(axh[ks], sb + aoff + ks*32);
        ldsm4(axl[ks], sb + 18432 + aoff + ks*32);
    }

    const uint32_t koff4 = (uint32_t)((lane & 7) + ((lane >> 4) << 3))*144 + (((lane >> 3) & 1) << 4);
    const size_t base = (size_t)(b*H_ + h) * T_ + t0;
    const int g = lane >> 2, tg = lane & 3;

    #pragma unroll
    for (int w = 0; w < 3; w++) {
        const uint32_t wbh = sb + 36864 + (uint32_t)w*18432;
        float sc[8][4];
        #pragma unroll
        for (int nf = 0; nf < 8; nf++)
            #pragma unroll
            for (int r = 0; r < 4; r++) sc[nf][r] = 0.0f;

        #pragma unroll
        for (int ks = 0; ks < 4; ks++) {
            #pragma unroll
            for (int p = 0; p < 4; p++) {
                uint32_t bh4[4], bl4[4];
                uint32_t ka = wbh + (uint32_t)p*2304 + koff4 + ks*32;
                ldsm4(bh4, ka);
                ldsm4(bl4, ka + 9216);
                mma_bf16(sc[2*p],   axh[ks], bh4);
                mma_bf16(sc[2*p],   axh[ks], bl4);
                mma_bf16(sc[2*p],   axl[ks], bh4);
                mma_bf16(sc[2*p+1], axh[ks], bh4 + 2);
                mma_bf16(sc[2*p+1], axh[ks], bl4 + 2);
                mma_bf16(sc[2*p+1], axl[ks], bh4 + 2);
            }
        }

        // ---- epilogue ----
        __nv_bfloat16* Ghi = (w == 0) ? g_qhi : (w == 1) ? g_khi : g_vhi;
        __nv_bfloat16* Glo = (w == 0) ? g_qlo : (w == 1) ? g_klo : g_vlo;
        #pragma unroll
        for (int nf = 0; nf < 8; nf++) {
            const int col = nf*8 + tg*2;
            #pragma unroll
            for (int h2 = 0; h2 < 2; h2++) {
                const int row = wid*16 + g + h2*8;
                float c0 = sc[nf][2*h2], c1 = sc[nf][2*h2+1];
                if (w == 1) {
                    int t = t0 + row;
                    c0 = (c0*(1.0f/32.0f) + Er[(size_t)col*T_ + t]) * LOG2E_;
                    c1 = (c1*(1.0f/32.0f) + Er[(size_t)(col+1)*T_ + t]) * LOG2E_;
                }
                uint32_t hi, lo;
                split2(c0, c1, hi, lo);
                size_t idx = (base + row)*S_ + col;
                *(uint32_t*)&Ghi[idx] = hi;
                *(uint32_t*)&Glo[idx] = lo;
            }
        }
    }
}

// ---------------------------------------------------------------------------
// Kernel 2: flash attention on mma.sync. BM=128, BN=64, D=64, 8 warps.
// 2-stage cp.async pipeline, Q fragments hoisted, K as n16 ldsm4 pairs.
// smem: Qh 0, Ql 18432, 2 bufs at 36864 + s*36864
//   (buf: Kh +0, Kl +9216, Vh +18432, Vl +27648). Total 110592 B.
// __launch_bounds__(256, 2) -> 2 CTAs/SM (221 KB smem, regs capped @128).
// ---------------------------------------------------------------------------
__global__ __launch_bounds__(256, 2) void attn_mma_kernel()
{
    extern __shared__ __align__(16) char asmem[];
    const uint32_t sb = smem_u32(asmem);
    const int tid = threadIdx.x, wid = tid >> 5, lane = tid & 31;
    const int qi = (int)gridDim.x - 1 - (int)blockIdx.x;   // big tiles first
    const int bh = blockIdx.y, t0 = qi * 128;

    const __nv_bfloat16* qh = g_qhi + (size_t)bh*T_*S_;
    const __nv_bfloat16* ql = g_qlo + (size_t)bh*T_*S_;
    const __nv_bfloat16* kh = g_khi + (size_t)bh*T_*S_;
    const __nv_bfloat16* kl = g_klo + (size_t)bh*T_*S_;
    const __nv_bfloat16* vh = g_vhi + (size_t)bh*T_*S_;
    const __nv_bfloat16* vl = g_vlo + (size_t)bh*T_*S_;

    // group: Q (hi+lo)
    #pragma unroll
    for (int it = 0; it < 4; it++) {
        int idx = it*256 + tid, row = idx >> 3, ch = idx & 7;
        uint32_t so = (uint32_t)row*144 + ch*16;
        size_t go = (size_t)(t0 + row)*64 + ch*8;
        cpa16(sb + so, qh + go);
        cpa16(sb + 18432 + so, ql + go);
    }
    asm volatile("cp.async.commit_group;" ::: "memory");

#define APREF(jj, bb) do {                                                      \
        uint32_t base_ = sb + 36864 + (uint32_t)(bb)*36864;                     \
        _Pragma("unroll")                                                       \
        for (int it_ = 0; it_ < 2; it_++) {                                     \
            int idx_ = it_*256 + tid, row_ = idx_ >> 3, ch_ = idx_ & 7;         \
            uint32_t so_ = (uint32_t)row_*144 + ch_*16;                         \
            size_t go_ = (size_t)((jj)*64 + row_)*64 + ch_*8;                   \
            cpa16(base_ + so_,         kh + go_);                               \
            cpa16(base_ + 9216  + so_, kl + go_);                               \
            cpa16(base_ + 18432 + so_, vh + go_);                               \
            cpa16(base_ + 27648 + so_, vl + go_);                               \
        }                                                                       \
        asm volatile("cp.async.commit_group;" ::: "memory");                    \
    } while (0)

    const int jmax = 2*qi + 1;
    APREF(0, 0);

    // wait Q (allow K/V group 0 to stay in flight), hoist Q fragments
    asm volatile("cp.async.wait_group 1;" ::: "memory");
    __syncthreads();
    const uint32_t qoff = (uint32_t)(wid*16 + (lane & 15))*144 + ((lane >> 4) * 16);
    uint32_t aqh[4][4], aql[4][4];
    #pragma unroll
    for (int ks = 0; ks < 4; ks++) {
        ldsm4(aqh[ks], sb + qoff + ks*32);
        ldsm4(aql[ks], sb + 18432 + qoff + ks*32);
    }

    const uint32_t koff4 = (uint32_t)((lane & 7) + ((lane >> 4) << 3))*144 + (((lane >> 3) & 1) << 4);
    const uint32_t voff = (uint32_t)(((lane >> 3) & 1)*8 + (lane & 7))*144 + ((lane >> 4) * 16);

    float m0 = -1e30f, m1 = -1e30f, l0 = 0.0f, l1 = 0.0f;
    float o[8][4];
    #pragma unroll
    for (int nf = 0; nf < 8; nf++)
        #pragma unroll
        for (int r = 0; r < 4; r++) o[nf][r] = 0.0f;

    for (int j = 0; j <= jmax; j++) {
        const int buf = j & 1;
        if (j < jmax) {
            APREF(j + 1, buf ^ 1);
            asm volatile("cp.async.wait_group 1;" ::: "memory");
        } else {
            asm volatile("cp.async.wait_group 0;" ::: "memory");
        }
        __syncthreads();

        const uint32_t kbb = sb + 36864 + (uint32_t)buf*36864;
        const uint32_t vbb = kbb + 18432;

        // ---- S = Q @ K2^T (3-term bf16 split; K via n16 ldsm4 pairs) ----
        float sc[8][4];
        #pragma unroll
        for (int nf = 0; nf < 8; nf++)
            #pragma unroll
            for (int r = 0; r < 4; r++) sc[nf][r] = 0.0f;

        #pragma unroll
        for (int ks = 0; ks < 4; ks++) {
            #pragma unroll
            for (int p = 0; p < 4; p++) {
                uint32_t bh4[4], bl4[4];
                uint32_t ka = kbb + (uint32_t)p*2304 + koff4 + ks*32;
                ldsm4(bh4, ka);
                ldsm4(bl4, ka + 9216);
                mma_bf16(sc[2*p],   aqh[ks], bh4);
                mma_bf16(sc[2*p],   aqh[ks], bl4);
                mma_bf16(sc[2*p],   aql[ks], bh4);
                mma_bf16(sc[2*p+1], aqh[ks], bh4 + 2);
                mma_bf16(sc[2*p+1], aqh[ks], bl4 + 2);
                mma_bf16(sc[2*p+1], aql[ks], bh4 + 2);
            }
        }

        // ---- causal mask (diagonal-straddling tiles only) ----
        if (j >= 2*qi) {
            const int rb = t0 + wid*16 + (lane >> 2);
            const int cb = j*64 + (lane & 3)*2;
            #pragma unroll
            for (int nf = 0; nf < 8; nf++) {
                int c = cb + nf*8;
                if (c     > rb)     sc[nf][0] = -1e30f;
                if (c + 1 > rb)     sc[nf][1] = -1e30f;
                if (c     > rb + 8) sc[nf][2] = -1e30f;
                if (c + 1 > rb + 8) sc[nf][3] = -1e30f;
            }
        }

        // ---- online softmax (base-2; log2e folded into k2) ----
        float rm0 = -1e30f, rm1 = -1e30f;
        #pragma unroll
        for (int nf = 0; nf < 8; nf++) {
            rm0 = fmaxf(rm0, fmaxf(sc[nf][0], sc[nf][1]));
            rm1 = fmaxf(rm1, fmaxf(sc[nf][2], sc[nf][3]));
        }
        rm0 = fmaxf(rm0, __shfl_xor_sync(0xffffffffu, rm0, 1));
        rm0 = fmaxf(rm0, __shfl_xor_sync(0xffffffffu, rm0, 2));
        rm1 = fmaxf(rm1, __shfl_xor_sync(0xffffffffu, rm1, 1));
        rm1 = fmaxf(rm1, __shfl_xor_sync(0xffffffffu, rm1, 2));
        float mn0 = fmaxf(m0, rm0), mn1 = fmaxf(m1, rm1);
        float a0 = fexp2(m0 - mn0), a1 = fexp2(m1 - mn1);
        m0 = mn0; m1 = mn1;

        float rs0 = 0.0f, rs1 = 0.0f;
        #pragma unroll
        for (int nf = 0; nf < 8; nf++) {
            sc[nf][0] = fexp2(sc[nf][0] - mn0);
            sc[nf][1] = fexp2(sc[nf][1] - mn0);
            sc[nf][2] = fexp2(sc[nf][2] - mn1);
            sc[nf][3] = fexp2(sc[nf][3] - mn1);
            rs0 += sc[nf][0] + sc[nf][1];
            rs1 += sc[nf][2] + sc[nf][3];
        }
        rs0 += __shfl_xor_sync(0xffffffffu, rs0, 1);
        rs0 += __shfl_xor_sync(0xffffffffu, rs0, 2);
        rs1 += __shfl_xor_sync(0xffffffffu, rs1, 1);
        rs1 += __shfl_xor_sync(0xffffffffu, rs1, 2);
        l0 = l0*a0 + rs0;
        l1 = l1*a1 + rs1;
        #pragma unroll
        for (int nf = 0; nf < 8; nf++) {
            o[nf][0] *= a0; o[nf][1] *= a0;
            o[nf][2] *= a1; o[nf][3] *= a1;
        }

        // ---- pack P fragments (C frag pairs -> A frags), hi/lo split ----
        uint32_t ph[4][4], pl[4][4];
        #pragma unroll
        for (int kb = 0; kb < 4; kb++) {
            const float* s0 = sc[2*kb];
            const float* s1 = sc[2*kb+1];
            float rr[8] = {s0[0], s0[1], s0[2], s0[3], s1[0], s1[1], s1[2], s1[3]};
            #pragma unroll
            for (int q2 = 0; q2 < 4; q2++)
                split2(rr[q2*2], rr[q2*2+1], ph[kb][q2], pl[kb][q2]);
        }

        // ---- O += P @ V (3-term bf16 split; V via ldmatrix.trans) ----
        #pragma unroll
        for (int kb = 0; kb < 4; kb++) {
            #pragma unroll
            for (int np = 0; np < 4; np++) {
                uint32_t v4h[4], v4l[4];
                uint32_t va = vbb + (uint32_t)kb*2304 + voff + np*32;
                ldsm4t(v4h, va);
                ldsm4t(v4l, va + 9216);
                mma_bf16(o[2*np],   ph[kb], v4h);
                mma_bf16(o[2*np],   ph[kb], v4l);
                mma_bf16(o[2*np],   pl[kb], v4h);
                mma_bf16(o[2*np+1], ph[kb], v4h + 2);
                mma_bf16(o[2*np+1], ph[kb], v4l + 2);
                mma_bf16(o[2*np+1], pl[kb], v4h + 2);
            }
        }
        __syncthreads();   // protect buffer reuse by next iteration's APREF
    }

    // ---- epilogue: normalize, stage [d][t] in smem, write Z hi/lo e-major ----
    float* stage = (float*)(asmem + 36864);   // [64][132] floats
    {
        float inv0 = 1.0f / l0, inv1 = 1.0f / l1;
        const int g = lane >> 2, tg = lane & 3;
        const int tl = wid*16 + g;
        #pragma unroll
        for (int nf = 0; nf < 8; nf++) {
            int d = nf*8 + tg*2;
            stage[d*132 + tl]           = o[nf][0] * inv0;
            stage[(d+1)*132 + tl]       = o[nf][1] * inv0;
            stage[d*132 + tl + 8]       = o[nf][2] * inv1;
            stage[(d+1)*132 + tl + 8]   = o[nf][3] * inv1;
        }
    }
    __syncthreads();

    const int b = bh >> 4, h = bh & 15;
    const size_t basez = ((size_t)b*E_ + h*S_) * T_;
    #pragma unroll
    for (int it = 0; it < 32; it++) {
        int idx = it*256 + tid;
        int d = idx >> 7, t = idx & 127;
        float y = stage[d*132 + t];
        __nv_bfloat16 hi = __float2bfloat16(y);
        size_t off = basez + (size_t)d*T_ + t0 + t;
        g_zhi[off] = hi;
        g_zlo[off] = __float2bfloat16(y - __bfloat162float(hi));
    }
}

// ---------------------------------------------------------------------------
// Kernel 3a: Wr -> bf16 hi/lo split
// ---------------------------------------------------------------------------
__global__ __launch_bounds__(256) void wconv_kernel(const float* __restrict__ Wr)
{
    size_t i = ((size_t)blockIdx.x*256 + threadIdx.x) * 4;
    float4 w = *(const float4*)&Wr[i];
    float v[4] = {w.x, w.y, w.z, w.w};
    #pragma unroll
    for (int q = 0; q < 4; q++) {
        __nv_bfloat16 hi = __float2bfloat16(v[q]);
        g_whi[i+q] = hi;
        g_wlo[i+q] = __float2bfloat16(v[q] - __bfloat162float(hi));
    }
}

// ---------------------------------------------------------------------------
// Kernel 3b: output projection via mma.sync (bf16, 3-term split).
// 128x128 CTA tile, 4 warps of 64x64 (ratio mma:ldsm4 = 6 -> tensor-bound),
// 128 threads, BK=32 double-buffered, 2 CTAs/SM.
// ---------------------------------------------------------------------------
#define PTILE_ (128*80)
#define PBUF_  (4*PTILE_)
__global__ __launch_bounds__(128) void proj_mma_kernel(
    const float* __restrict__ br, float* __restrict__ out)
{
    extern __shared__ __align__(128) char ps[];
    const uint32_t sb = smem_u32(ps);
    const int tid = threadIdx.x, wid = tid >> 5, lane = tid & 31;
    const int n0 = blockIdx.x * 128, m0 = blockIdx.y * 128;
    const int wm = wid >> 1, wn = wid & 1;

    float acc[4][8][4];
    #pragma unroll
    for (int mf = 0; mf < 4; mf++)
        #pragma unroll
        for (int nf = 0; nf < 8; nf++)
            #pragma unroll
            for (int r = 0; r < 4; r++) acc[mf][nf][r] = 0.0f;

    #define ISSUE(cc, bb) do {                                                  \
        const int k0i = (cc) * 32;                                              \
        uint32_t base = sb + (bb) * PBUF_;                                      \
        _Pragma("unroll")                                                       \
        for (int q = 0; q < 4; q++) {                                           \
            int row = (tid >> 2) + q*32;                                        \
            uint32_t soff = (uint32_t)row*80 + (uint32_t)(tid & 3)*16;          \
            size_t ga = (size_t)(m0 + row)*E_ + k0i + (tid & 3)*8;              \
            size_t gb = (size_t)(n0 + row)*E_ + k0i + (tid & 3)*8;              \
            cpa16(base + 0*PTILE_ + soff, g_zhi + ga);                          \
            cpa16(base + 1*PTILE_ + soff, g_zlo + ga);                          \
            cpa16(base + 2*PTILE_ + soff, g_whi + gb);                          \
            cpa16(base + 3*PTILE_ + soff, g_wlo + gb);                          \
        }                                                                       \
        asm volatile("cp.async.commit_group;" ::: "memory");                    \
    } while (0)

    const uint32_t koff4p = (uint32_t)((lane & 7) + ((lane >> 4) << 3))*80 + (((lane >> 3) & 1) << 4);
    const int am = lane & 15;

    ISSUE(0, 0);
    for (int c = 0; c < 32; c++) {
        const int buf = c & 1;
        if (c + 1 < 32) {
            ISSUE(c + 1, buf ^ 1);
            asm volatile("cp.async.wait_group 1;" ::: "memory");
        } else {
            asm volatile("cp.async.wait_group 0;" ::: "memory");
        }
        __syncthreads();

        const uint32_t Ah = sb + buf*PBUF_;
        const uint32_t Al = Ah + PTILE_;
        const uint32_t Bh = Ah + 2*PTILE_;
        const uint32_t Bl = Ah + 3*PTILE_;

        #pragma unroll
        for (int ks = 0; ks < 2; ks++) {
            uint32_t ah[4][4], al[4][4], bh4[4][4], bl4[4][4];
            const uint32_t akoff = (uint32_t)(ks*32 + (lane >> 4)*16);
            #pragma unroll
            for (int mf = 0; mf < 4; mf++) {
                uint32_t ro = (uint32_t)(wm*64 + mf*16 + am)*80 + akoff;
                ldsm4(ah[mf], Ah + ro);
                ldsm4(al[mf], Al + ro);
            }
            #pragma unroll
            for (int p = 0; p < 4; p++) {
                uint32_t ro = (uint32_t)(wn*64 + p*16)*80 + koff4p + ks*32;
                ldsm4(bh4[p], Bh + ro);
                ldsm4(bl4[p], Bl + ro);
            }
            #pragma unroll
            for (int mf = 0; mf < 4; mf++)
                #pragma unroll
                for (int p = 0; p < 4; p++) {
                    mma_bf16(acc[mf][2*p],   ah[mf], bh4[p]);
                    mma_bf16(acc[mf][2*p],   ah[mf], bl4[p]);
                    mma_bf16(acc[mf][2*p],   al[mf], bh4[p]);
                    mma_bf16(acc[mf][2*p+1], ah[mf], bh4[p] + 2);
                    mma_bf16(acc[mf][2*p+1], ah[mf], bl4[p] + 2);
                    mma_bf16(acc[mf][2*p+1], al[mf], bh4[p] + 2);
                }
        }
        __syncthreads();
    }

    const int g = lane >> 2, tg = lane & 3;
    #pragma unroll
    for (int nf = 0; nf < 8; nf++) {
        const int col = n0 + wn*64 + nf*8 + tg*2;
        float2 bb = *(const float2*)&br[col];
        #pragma unroll
        for (int mf = 0; mf < 4; mf++) {
            const int row = m0 + wm*64 + mf*16 + g;
            float2 v0 = make_float2(acc[mf][nf][0] + bb.x, acc[mf][nf][1] + bb.y);
            float2 v1 = make_float2(acc[mf][nf][2] + bb.x, acc[mf][nf][3] + bb.y);
            *(float2*)&out[(size_t)row*E_ + col]       = v0;
            *(float2*)&out[(size_t)(row + 8)*E_ + col] = v1;
        }
    }
}

// ---------------------------------------------------------------------------
extern "C" void kernel_launch(void* const* d_in, const int* in_sizes, int n_in,
                              void* d_out, int out_size)
{
    const float* x  = (const float*)d_in[0];
    const float* Wq = (const float*)d_in[1];
    const float* Wk = (const float*)d_in[2];
    const float* Wv = (const float*)d_in[3];
    const float* Er = (const float*)d_in[4];
    const float* Wr = (const float*)d_in[5];
    const float* br = (const float*)d_in[6];
    float* out = (float*)d_out;

    const int smem_qkv = 92160;
    cudaFuncSetAttribute(qkv_mma_kernel,
                         cudaFuncAttributeMaxDynamicSharedMemorySize, smem_qkv);
    qkv_mma_kernel<<<dim3(T_/128, H_, B_), 256, smem_qkv>>>(x, Wq, Wk, Wv, Er);

    wconv_kernel<<<(E_*E_)/(256*4), 256>>>(Wr);

    const int smem_attn = 110592;   // 2-stage; 2 CTAs/SM
    cudaFuncSetAttribute(attn_mma_kernel,
                         cudaFuncAttributeMaxDynamicSharedMemorySize, smem_attn);
    attn_mma_kernel<<<dim3(T_/128, BH_), 256, smem_attn>>>();

    const int smem_proj = 2 * PBUF_;  // 81920; 2 CTAs/SM
    cudaFuncSetAttribute(proj_mma_kernel,
                         cudaFuncAttributeMaxDynamicSharedMemorySize, smem_proj);
    proj_mma_kernel<<<dim3(E_/128, (B_*T_)/128), 128, smem_proj>>>(br, out);
}

// round 12
// speedup vs baseline: 1.0507x; 1.0228x over previous
#include <cuda_runtime.h>
#include <cuda_bf16.h>
#include <math.h>
#include <stdint.h>

#define T_ 2048
#define B_ 2
#define E_ 1024
#define H_ 16
#define S_ 64
#define BH_ (B_*H_)
#define LOG2E_ 1.4426950408889634f

// Scratch (static device globals; allocation-free per harness rules)
__device__ __nv_bfloat16 g_qhi[B_*H_*T_*S_];   // [bh][t][d] q hi
__device__ __nv_bfloat16 g_qlo[B_*H_*T_*S_];
__device__ __nv_bfloat16 g_khi[B_*H_*T_*S_];   // [bh][r][d] k2 = (k/32 + Er)*log2e
__device__ __nv_bfloat16 g_klo[B_*H_*T_*S_];
__device__ __nv_bfloat16 g_vhi[B_*H_*T_*S_];   // [bh][r][d]
__device__ __nv_bfloat16 g_vlo[B_*H_*T_*S_];
__device__ __nv_bfloat16 g_zhi[B_*E_*T_];      // Z (proj input) hi, flat [4096][1024]
__device__ __nv_bfloat16 g_zlo[B_*E_*T_];
__device__ __nv_bfloat16 g_whi[E_*E_];         // Wr hi
__device__ __nv_bfloat16 g_wlo[E_*E_];

// ===========================================================================
// mma.sync / ldmatrix / cp.async helpers
// ===========================================================================
__device__ __forceinline__ uint32_t smem_u32(const void* p) {
    uint32_t a;
    asm("{ .reg .u64 t; cvta.to.shared.u64 t, %1; cvt.u32.u64 %0, t; }"
        : "=r"(a) : "l"(p));
    return a;
}
__device__ __forceinline__ void ldsm4(uint32_t* r, uint32_t addr) {
    asm volatile("ldmatrix.sync.aligned.m8n8.x4.shared.b16 {%0,%1,%2,%3}, [%4];"
                 : "=r"(r[0]), "=r"(r[1]), "=r"(r[2]), "=r"(r[3]) : "r"(addr));
}
__device__ __forceinline__ void ldsm4t(uint32_t* r, uint32_t addr) {
    asm volatile("ldmatrix.sync.aligned.m8n8.x4.trans.shared.b16 {%0,%1,%2,%3}, [%4];"
                 : "=r"(r[0]), "=r"(r[1]), "=r"(r[2]), "=r"(r[3]) : "r"(addr));
}
__device__ __forceinline__ void mma_bf16(float* c, const uint32_t* a, const uint32_t* b) {
    asm volatile(
        "mma.sync.aligned.m16n8k16.row.col.f32.bf16.bf16.f32 "
        "{%0,%1,%2,%3}, {%4,%5,%6,%7}, {%8,%9}, {%0,%1,%2,%3};"
        : "+f"(c[0]), "+f"(c[1]), "+f"(c[2]), "+f"(c[3])
        : "r"(a[0]), "r"(a[1]), "r"(a[2]), "r"(a[3]), "r"(b[0]), "r"(b[1]));
}
__device__ __forceinline__ void cpa16(uint32_t dst, const void* src) {
    asm volatile("cp.async.cg.shared.global [%0], [%1], 16;" :: "r"(dst), "l"(src));
}
__device__ __forceinline__ float fexp2(float x) {
    float y; asm("ex2.approx.ftz.f32 %0, %1;" : "=f"(y) : "f"(x)); return y;
}
__device__ __forceinline__ uint32_t pack_bf2(float x, float y) {
    __nv_bfloat16 hx = __float2bfloat16(x), hy = __float2bfloat16(y);
    return (uint32_t)__bfloat16_as_ushort(hx) |
           ((uint32_t)__bfloat16_as_ushort(hy) << 16);
}
// split two floats -> hi-packed u32 + lo-packed u32
__device__ __forceinline__ void split2(float a, float b, uint32_t& hi, uint32_t& lo) {
    __nv_bfloat16 h0 = __float2bfloat16(a), h1 = __float2bfloat16(b);
    hi = (uint32_t)__bfloat16_as_ushort(h0) | ((uint32_t)__bfloat16_as_ushort(h1) << 16);
    lo = pack_bf2(a - __bfloat162float(h0), b - __bfloat162float(h1));
}

// ---------------------------------------------------------------------------
// Kernel 1: QKV projections on mma.sync (3-term bf16 split). Unchanged.
// ---------------------------------------------------------------------------
__global__ __launch_bounds__(256) void qkv_mma_kernel(
    const float* __restrict__ x,   // [T,B,E]
    const float* __restrict__ Wq,  // [H,S,S]
    const float* __restrict__ Wk,
    const float* __restrict__ Wv,
    const float* __restrict__ Er)  // [S,T]
{
    extern __shared__ __align__(16) char qsmem[];
    const uint32_t sb = smem_u32(qsmem);
    const int tid = threadIdx.x, wid = tid >> 5, lane = tid & 31;
    const int h = blockIdx.y, b = blockIdx.z;
    const int t0 = blockIdx.x * 128;

    // ---- load + split x tile [128][64] ----
    {
        const int r  = tid >> 1;
        const int d0 = (tid & 1) * 32;
        #pragma unroll
        for (int q = 0; q < 8; q++) {
            float4 v4 = *(const float4*)&x[(size_t)(t0 + r)*(B_*E_) + b*E_ + h*S_ + d0 + q*4];
            uint32_t h0, l0, h1, l1;
            split2(v4.x, v4.y, h0, l0);
            split2(v4.z, v4.w, h1, l1);
            uint32_t off = (uint32_t)r*144 + (uint32_t)(d0 + q*4)*2;
            *(uint2*)(qsmem + off)          = make_uint2(h0, h1);
            *(uint2*)(qsmem + 18432 + off)  = make_uint2(l0, l1);
        }
    }
    // ---- load + split W tiles [64][64] x 3 ----
    {
        const float* W[3] = { Wq + h*4096, Wk + h*4096, Wv + h*4096 };
        const int dd = tid >> 2;
        const int s0 = (tid & 3) * 16;
        #pragma unroll
        for (int w = 0; w < 3; w++) {
            uint32_t basew = 36864 + (uint32_t)w*18432;
            #pragma unroll
            for (int q = 0; q < 4; q++) {
                float4 w4 = *(const float4*)&W[w][dd*64 + s0 + q*4];
                uint32_t h0, l0, h1, l1;
                split2(w4.x, w4.y, h0, l0);
                split2(w4.z, w4.w, h1, l1);
                uint32_t off = (uint32_t)dd*144 + (uint32_t)(s0 + q*4)*2;
                *(uint2*)(qsmem + basew + off)         = make_uint2(h0, h1);
                *(uint2*)(qsmem + basew + 9216 + off)  = make_uint2(l0, l1);
            }
        }
    }
    __syncthreads();

    // ---- hoist A (x) fragments ----
    const uint32_t aoff = (uint32_t)(wid*16 + (lane & 15))*144 + ((lane >> 4) * 16);
    uint32_t axh[4][4], axl[4][4];
    #pragma unroll
    for (int ks = 0; ks < 4; ks++) {
        ldsm4(axh[ks], sb + aoff + ks*32);
        ldsm4(axl[ks], sb + 18432 + aoff + ks*32);
    }

    const uint32_t koff4 = (uint32_t)((lane & 7) + ((lane >> 4) << 3))*144 + (((lane >> 3) & 1) << 4);
    const size_t base = (size_t)(b*H_ + h) * T_ + t0;
    const int g = lane >> 2, tg = lane & 3;

    #pragma unroll
    for (int w = 0; w < 3; w++) {
        const uint32_t wbh = sb + 36864 + (uint32_t)w*18432;
        float sc[8][4];
        #pragma unroll
        for (int nf = 0; nf < 8; nf++)
            #pragma unroll
            for (int r = 0; r < 4; r++) sc[nf][r] = 0.0f;

        #pragma unroll
        for (int ks = 0; ks < 4; ks++) {
            #pragma unroll
            for (int p = 0; p < 4; p++) {
                uint32_t bh4[4], bl4[4];
                uint32_t ka = wbh + (uint32_t)p*2304 + koff4 + ks*32;
                ldsm4(bh4, ka);
                ldsm4(bl4, ka + 9216);
                mma_bf16(sc[2*p],   axh[ks], bh4);
                mma_bf16(sc[2*p],   axh[ks], bl4);
                mma_bf16(sc[2*p],   axl[ks], bh4);
                mma_bf16(sc[2*p+1], axh[ks], bh4 + 2);
                mma_bf16(sc[2*p+1], axh[ks], bl4 + 2);
                mma_bf16(sc[2*p+1], axl[ks], bh4 + 2);
            }
        }

        // ---- epilogue ----
        __nv_bfloat16* Ghi = (w == 0) ? g_qhi : (w == 1) ? g_khi : g_vhi;
        __nv_bfloat16* Glo = (w == 0) ? g_qlo : (w == 1) ? g_klo : g_vlo;
        #pragma unroll
        for (int nf = 0; nf < 8; nf++) {
            const int col = nf*8 + tg*2;
            #pragma unroll
            for (int h2 = 0; h2 < 2; h2++) {
                const int row = wid*16 + g + h2*8;
                float c0 = sc[nf][2*h2], c1 = sc[nf][2*h2+1];
                if (w == 1) {
                    int t = t0 + row;
                    c0 = (c0*(1.0f/32.0f) + Er[(size_t)col*T_ + t]) * LOG2E_;
                    c1 = (c1*(1.0f/32.0f) + Er[(size_t)(col+1)*T_ + t]) * LOG2E_;
                }
                uint32_t hi, lo;
                split2(c0, c1, hi, lo);
                size_t idx = (base + row)*S_ + col;
                *(uint32_t*)&Ghi[idx] = hi;
                *(uint32_t*)&Glo[idx] = lo;
            }
        }
    }
}

// ---------------------------------------------------------------------------
// Kernel 2: flash attention on mma.sync. BM=128, BN=64, D=64, 8 warps.
// 2-stage cp.async pipeline, only Q-hi fragments hoisted (register diet:
// fits 128 regs spill-free at 2 CTAs/SM). Q-lo reloaded per ks (1 ldsm4).
// smem: Qh 0, Ql 18432, 2 bufs at 36864 + s*36864. Total 110592 B.
// ---------------------------------------------------------------------------
__global__ __launch_bounds__(256, 2) void attn_mma_kernel()
{
    extern __shared__ __align__(16) char asmem[];
    const uint32_t sb = smem_u32(asmem);
    const int tid = threadIdx.x, wid = tid >> 5, lane = tid & 31;
    const int qi = (int)gridDim.x - 1 - (int)blockIdx.x;   // big tiles first
    const int bh = blockIdx.y, t0 = qi * 128;

    const __nv_bfloat16* qh = g_qhi + (size_t)bh*T_*S_;
    const __nv_bfloat16* ql = g_qlo + (size_t)bh*T_*S_;
    const __nv_bfloat16* kh = g_khi + (size_t)bh*T_*S_;
    const __nv_bfloat16* kl = g_klo + (size_t)bh*T_*S_;
    const __nv_bfloat16* vh = g_vhi + (size_t)bh*T_*S_;
    const __nv_bfloat16* vl = g_vlo + (size_t)bh*T_*S_;

    // group: Q (hi+lo)
    #pragma unroll
    for (int it = 0; it < 4; it++) {
        int idx = it*256 + tid, row = idx >> 3, ch = idx & 7;
        uint32_t so = (uint32_t)row*144 + ch*16;
        size_t go = (size_t)(t0 + row)*64 + ch*8;
        cpa16(sb + so, qh + go);
        cpa16(sb + 18432 + so, ql + go);
    }
    asm volatile("cp.async.commit_group;" ::: "memory");

#define APREF(jj, bb) do {                                                      \
        uint32_t base_ = sb + 36864 + (uint32_t)(bb)*36864;                     \
        _Pragma("unroll")                                                       \
        for (int it_ = 0; it_ < 2; it_++) {                                     \
            int idx_ = it_*256 + tid, row_ = idx_ >> 3, ch_ = idx_ & 7;         \
            uint32_t so_ = (uint32_t)row_*144 + ch_*16;                         \
            size_t go_ = (size_t)((jj)*64 + row_)*64 + ch_*8;                   \
            cpa16(base_ + so_,         kh + go_);                               \
            cpa16(base_ + 9216  + so_, kl + go_);                               \
            cpa16(base_ + 18432 + so_, vh + go_);                               \
            cpa16(base_ + 27648 + so_, vl + go_);                               \
        }                                                                       \
        asm volatile("cp.async.commit_group;" ::: "memory");                    \
    } while (0)

    const int jmax = 2*qi + 1;
    APREF(0, 0);

    // wait Q (allow K/V group 0 to stay in flight), hoist Q-hi fragments only
    asm volatile("cp.async.wait_group 1;" ::: "memory");
    __syncthreads();
    const uint32_t qoff = (uint32_t)(wid*16 + (lane & 15))*144 + ((lane >> 4) * 16);
    uint32_t aqh[4][4];
    #pragma unroll
    for (int ks = 0; ks < 4; ks++)
        ldsm4(aqh[ks], sb + qoff + ks*32);

    const uint32_t koff4 = (uint32_t)((lane & 7) + ((lane >> 4) << 3))*144 + (((lane >> 3) & 1) << 4);
    const uint32_t voff = (uint32_t)(((lane >> 3) & 1)*8 + (lane & 7))*144 + ((lane >> 4) * 16);

    float m0 = -1e30f, m1 = -1e30f, l0 = 0.0f, l1 = 0.0f;
    float o[8][4];
    #pragma unroll
    for (int nf = 0; nf < 8; nf++)
        #pragma unroll
        for (int r = 0; r < 4; r++) o[nf][r] = 0.0f;

    for (int j = 0; j <= jmax; j++) {
        const int buf = j & 1;
        if (j < jmax) {
            APREF(j + 1, buf ^ 1);
            asm volatile("cp.async.wait_group 1;" ::: "memory");
        } else {
            asm volatile("cp.async.wait_group 0;" ::: "memory");
        }
        __syncthreads();

        const uint32_t kbb = sb + 36864 + (uint32_t)buf*36864;
        const uint32_t vbb = kbb + 18432;

        // ---- S = Q @ K2^T (3-term bf16 split; q-lo reloaded per ks) ----
        float sc[8][4];
        #pragma unroll
        for (int nf = 0; nf < 8; nf++)
            #pragma unroll
            for (int r = 0; r < 4; r++) sc[nf][r] = 0.0f;

        #pragma unroll
        for (int ks = 0; ks < 4; ks++) {
            uint32_t aql[4];
            ldsm4(aql, sb + 18432 + qoff + ks*32);
            #pragma unroll
            for (int p = 0; p < 4; p++) {
                uint32_t bh4[4], bl4[4];
                uint32_t ka = kbb + (uint32_t)p*2304 + koff4 + ks*32;
                ldsm4(bh4, ka);
                ldsm4(bl4, ka + 9216);
                mma_bf16(sc[2*p],   aqh[ks], bh4);
                mma_bf16(sc[2*p],   aqh[ks], bl4);
                mma_bf16(sc[2*p],   aql,     bh4);
                mma_bf16(sc[2*p+1], aqh[ks], bh4 + 2);
                mma_bf16(sc[2*p+1], aqh[ks], bl4 + 2);
                mma_bf16(sc[2*p+1], aql,     bh4 + 2);
            }
        }

        // ---- causal mask (diagonal-straddling tiles only) ----
        if (j >= 2*qi) {
            const int rb = t0 + wid*16 + (lane >> 2);
            const int cb = j*64 + (lane & 3)*2;
            #pragma unroll
            for (int nf = 0; nf < 8; nf++) {
                int c = cb + nf*8;
                if (c     > rb)     sc[nf][0] = -1e30f;
                if (c + 1 > rb)     sc[nf][1] = -1e30f;
                if (c     > rb + 8) sc[nf][2] = -1e30f;
                if (c + 1 > rb + 8) sc[nf][3] = -1e30f;
            }
        }

        // ---- online softmax (base-2; log2e folded into k2) ----
        float rm0 = -1e30f, rm1 = -1e30f;
        #pragma unroll
        for (int nf = 0; nf < 8; nf++) {
            rm0 = fmaxf(rm0, fmaxf(sc[nf][0], sc[nf][1]));
            rm1 = fmaxf(rm1, fmaxf(sc[nf][2], sc[nf][3]));
        }
        rm0 = fmaxf(rm0, __shfl_xor_sync(0xffffffffu, rm0, 1));
        rm0 = fmaxf(rm0, __shfl_xor_sync(0xffffffffu, rm0, 2));
        rm1 = fmaxf(rm1, __shfl_xor_sync(0xffffffffu, rm1, 1));
        rm1 = fmaxf(rm1, __shfl_xor_sync(0xffffffffu, rm1, 2));
        float mn0 = fmaxf(m0, rm0), mn1 = fmaxf(m1, rm1);
        float a0 = fexp2(m0 - mn0), a1 = fexp2(m1 - mn1);
        m0 = mn0; m1 = mn1;

        float rs0 = 0.0f, rs1 = 0.0f;
        #pragma unroll
        for (int nf = 0; nf < 8; nf++) {
            sc[nf][0] = fexp2(sc[nf][0] - mn0);
            sc[nf][1] = fexp2(sc[nf][1] - mn0);
            sc[nf][2] = fexp2(sc[nf][2] - mn1);
            sc[nf][3] = fexp2(sc[nf][3] - mn1);
            rs0 += sc[nf][0] + sc[nf][1];
            rs1 += sc[nf][2] + sc[nf][3];
        }
        rs0 += __shfl_xor_sync(0xffffffffu, rs0, 1);
        rs0 += __shfl_xor_sync(0xffffffffu, rs0, 2);
        rs1 += __shfl_xor_sync(0xffffffffu, rs1, 1);
        rs1 += __shfl_xor_sync(0xffffffffu, rs1, 2);
        l0 = l0*a0 + rs0;
        l1 = l1*a1 + rs1;
        #pragma unroll
        for (int nf = 0; nf < 8; nf++) {
            o[nf][0] *= a0; o[nf][1] *= a0;
            o[nf][2] *= a1; o[nf][3] *= a1;
        }

        // ---- pack P fragments (C frag pairs -> A frags), hi/lo split ----
        uint32_t ph[4][4], pl[4][4];
        #pragma unroll
        for (int kb = 0; kb < 4; kb++) {
            const float* s0 = sc[2*kb];
            const float* s1 = sc[2*kb+1];
            float rr[8] = {s0[0], s0[1], s0[2], s0[3], s1[0], s1[1], s1[2], s1[3]};
            #pragma unroll
            for (int q2 = 0; q2 < 4; q2++)
                split2(rr[q2*2], rr[q2*2+1], ph[kb][q2], pl[kb][q2]);
        }

        // ---- O += P @ V (3-term bf16 split; V via ldmatrix.trans) ----
        #pragma unroll
        for (int kb = 0; kb < 4; kb++) {
            #pragma unroll
            for (int np = 0; np < 4; np++) {
                uint32_t v4h[4], v4l[4];
                uint32_t va = vbb + (uint32_t)kb*2304 + voff + np*32;
                ldsm4t(v4h, va);
                ldsm4t(v4l, va + 9216);
                mma_bf16(o[2*np],   ph[kb], v4h);
                mma_bf16(o[2*np],   ph[kb], v4l);
                mma_bf16(o[2*np],   pl[kb], v4h);
                mma_bf16(o[2*np+1], ph[kb], v4h + 2);
                mma_bf16(o[2*np+1], ph[kb], v4l + 2);
                mma_bf16(o[2*np+1], pl[kb], v4h + 2);
            }
        }
        __syncthreads();   // protect buffer reuse by next iteration's APREF
    }

    // ---- epilogue: normalize, stage [d][t] in smem, write Z hi/lo e-major ----
    float* stage = (float*)(asmem + 36864);   // [64][132] floats
    {
        float inv0 = 1.0f / l0, inv1 = 1.0f / l1;
        const int g = lane >> 2, tg = lane & 3;
        const int tl = wid*16 + g;
        #pragma unroll
        for (int nf = 0; nf < 8; nf++) {
            int d = nf*8 + tg*2;
            stage[d*132 + tl]           = o[nf][0] * inv0;
            stage[(d+1)*132 + tl]       = o[nf][1] * inv0;
            stage[d*132 + tl + 8]       = o[nf][2] * inv1;
            stage[(d+1)*132 + tl + 8]   = o[nf][3] * inv1;
        }
    }
    __syncthreads();

    const int b = bh >> 4, h = bh & 15;
    const size_t basez = ((size_t)b*E_ + h*S_) * T_;
    #pragma unroll
    for (int it = 0; it < 32; it++) {
        int idx = it*256 + tid;
        int d = idx >> 7, t = idx & 127;
        float y = stage[d*132 + t];
        __nv_bfloat16 hi = __float2bfloat16(y);
        size_t off = basez + (size_t)d*T_ + t0 + t;
        g_zhi[off] = hi;
        g_zlo[off] = __float2bfloat16(y - __bfloat162float(hi));
    }
}

// ---------------------------------------------------------------------------
// Kernel 3a: Wr -> bf16 hi/lo split
// ---------------------------------------------------------------------------
__global__ __launch_bounds__(256) void wconv_kernel(const float* __restrict__ Wr)
{
    size_t i = ((size_t)blockIdx.x*256 + threadIdx.x) * 4;
    float4 w = *(const float4*)&Wr[i];
    float v[4] = {w.x, w.y, w.z, w.w};
    #pragma unroll
    for (int q = 0; q < 4; q++) {
        __nv_bfloat16 hi = __float2bfloat16(v[q]);
        g_whi[i+q] = hi;
        g_wlo[i+q] = __float2bfloat16(v[q] - __bfloat162float(hi));
    }
}

// ---------------------------------------------------------------------------
// Kernel 3b: output projection via mma.sync (bf16, 3-term split).
// 128x128 CTA tile, 4 warps of 64x64, B fragments loaded per-p (reg diet).
// ---------------------------------------------------------------------------
#define PTILE_ (128*80)
#define PBUF_  (4*PTILE_)
__global__ __launch_bounds__(128) void proj_mma_kernel(
    const float* __restrict__ br, float* __restrict__ out)
{
    extern __shared__ __align__(128) char ps[];
    const uint32_t sb = smem_u32(ps);
    const int tid = threadIdx.x, wid = tid >> 5, lane = tid & 31;
    const int n0 = blockIdx.x * 128, m0 = blockIdx.y * 128;
    const int wm = wid >> 1, wn = wid & 1;

    float acc[4][8][4];
    #pragma unroll
    for (int mf = 0; mf < 4; mf++)
        #pragma unroll
        for (int nf = 0; nf < 8; nf++)
            #pragma unroll
            for (int r = 0; r < 4; r++) acc[mf][nf][r] = 0.0f;

    #define ISSUE(cc, bb) do {                                                  \
        const int k0i = (cc) * 32;                                              \
        uint32_t base = sb + (bb) * PBUF_;                                      \
        _Pragma("unroll")                                                       \
        for (int q = 0; q < 4; q++) {                                           \
            int row = (tid >> 2) + q*32;                                        \
            uint32_t soff = (uint32_t)row*80 + (uint32_t)(tid & 3)*16;          \
            size_t ga = (size_t)(m0 + row)*E_ + k0i + (tid & 3)*8;              \
            size_t gb = (size_t)(n0 + row)*E_ + k0i + (tid & 3)*8;              \
            cpa16(base + 0*PTILE_ + soff, g_zhi + ga);                          \
            cpa16(base + 1*PTILE_ + soff, g_zlo + ga);                          \
            cpa16(base + 2*PTILE_ + soff, g_whi + gb);                          \
            cpa16(base + 3*PTILE_ + soff, g_wlo + gb);                          \
        }                                                                       \
        asm volatile("cp.async.commit_group;" ::: "memory");                    \
    } while (0)

    const uint32_t koff4p = (uint32_t)((lane & 7) + ((lane >> 4) << 3))*80 + (((lane >> 3) & 1) << 4);
    const int am = lane & 15;

    ISSUE(0, 0);
    for (int c = 0; c < 32; c++) {
        const int buf = c & 1;
        if (c + 1 < 32) {
            ISSUE(c + 1, buf ^ 1);
            asm volatile("cp.async.wait_group 1;" ::: "memory");
        } else {
            asm volatile("cp.async.wait_group 0;" ::: "memory");
        }
        __syncthreads();

        const uint32_t Ah = sb + buf*PBUF_;
        const uint32_t Al = Ah + PTILE_;
        const uint32_t Bh = Ah + 2*PTILE_;
        const uint32_t Bl = Ah + 3*PTILE_;

        #pragma unroll
        for (int ks = 0; ks < 2; ks++) {
            uint32_t ah[4][4], al[4][4];
            const uint32_t akoff = (uint32_t)(ks*32 + (lane >> 4)*16);
            #pragma unroll
            for (int mf = 0; mf < 4; mf++) {
                uint32_t ro = (uint32_t)(wm*64 + mf*16 + am)*80 + akoff;
                ldsm4(ah[mf], Ah + ro);
                ldsm4(al[mf], Al + ro);
            }
            #pragma unroll
            for (int p = 0; p < 4; p++) {
                uint32_t bh4[4], bl4[4];
                uint32_t ro = (uint32_t)(wn*64 + p*16)*80 + koff4p + ks*32;
                ldsm4(bh4, Bh + ro);
                ldsm4(bl4, Bl + ro);
                #pragma unroll
                for (int mf = 0; mf < 4; mf++) {
                    mma_bf16(acc[mf][2*p],   ah[mf], bh4);
                    mma_bf16(acc[mf][2*p],   ah[mf], bl4);
                    mma_bf16(acc[mf][2*p],   al[mf], bh4);
                    mma_bf16(acc[mf][2*p+1], ah[mf], bh4 + 2);
                    mma_bf16(acc[mf][2*p+1], ah[mf], bl4 + 2);
                    mma_bf16(acc[mf][2*p+1], al[mf], bh4 + 2);
                }
            }
        }
        __syncthreads();
    }

    const int g = lane >> 2, tg = lane & 3;
    #pragma unroll
    for (int nf = 0; nf < 8; nf++) {
        const int col = n0 + wn*64 + nf*8 + tg*2;
        float2 bb = *(const float2*)&br[col];
        #pragma unroll
        for (int mf = 0; mf < 4; mf++) {
            const int row = m0 + wm*64 + mf*16 + g;
            float2 v0 = make_float2(acc[mf][nf][0] + bb.x, acc[mf][nf][1] + bb.y);
            float2 v1 = make_float2(acc[mf][nf][2] + bb.x, acc[mf][nf][3] + bb.y);
            *(float2*)&out[(size_t)row*E_ + col]       = v0;
            *(float2*)&out[(size_t)(row + 8)*E_ + col] = v1;
        }
    }
}

// ---------------------------------------------------------------------------
extern "C" void kernel_launch(void* const* d_in, const int* in_sizes, int n_in,
                              void* d_out, int out_size)
{
    const float* x  = (const float*)d_in[0];
    const float* Wq = (const float*)d_in[1];
    const float* Wk = (const float*)d_in[2];
    const float* Wv = (const float*)d_in[3];
    const float* Er = (const float*)d_in[4];
    const float* Wr = (const float*)d_in[5];
    const float* br = (const float*)d_in[6];
    float* out = (float*)d_out;

    const int smem_qkv = 92160;
    cudaFuncSetAttribute(qkv_mma_kernel,
                         cudaFuncAttributeMaxDynamicSharedMemorySize, smem_qkv);
    qkv_mma_kernel<<<dim3(T_/128, H_, B_), 256, smem_qkv>>>(x, Wq, Wk, Wv, Er);

    wconv_kernel<<<(E_*E_)/(256*4), 256>>>(Wr);

    const int smem_attn = 110592;   // 2-stage; 2 CTAs/SM
    cudaFuncSetAttribute(attn_mma_kernel,
                         cudaFuncAttributeMaxDynamicSharedMemorySize, smem_attn);
    attn_mma_kernel<<<dim3(T_/128, BH_), 256, smem_attn>>>();

    const int smem_proj = 2 * PBUF_;  // 81920; 2 CTAs/SM
    cudaFuncSetAttribute(proj_mma_kernel,
                         cudaFuncAttributeMaxDynamicSharedMemorySize, smem_proj);
    proj_mma_kernel<<<dim3(E_/128, (B_*T_)/128), 128, smem_proj>>>(br, out);
}

// round 13
// speedup vs baseline: 1.0718x; 1.0200x over previous
#include <cuda_runtime.h>
#include <cuda_bf16.h>
#include <math.h>
#include <stdint.h>

#define T_ 2048
#define B_ 2
#define E_ 1024
#define H_ 16
#define S_ 64
#define BH_ (B_*H_)
#define LOG2E_ 1.4426950408889634f

// Scratch (static device globals; allocation-free per harness rules)
__device__ __nv_bfloat16 g_qhi[B_*H_*T_*S_];   // [bh][t][d] q hi
__device__ __nv_bfloat16 g_qlo[B_*H_*T_*S_];
__device__ __nv_bfloat16 g_khi[B_*H_*T_*S_];   // [bh][r][d] k2 = (k/32 + Er)*log2e
__device__ __nv_bfloat16 g_klo[B_*H_*T_*S_];
__device__ __nv_bfloat16 g_vhi[B_*H_*T_*S_];   // [bh][r][d]
__device__ __nv_bfloat16 g_vlo[B_*H_*T_*S_];
__device__ __nv_bfloat16 g_zhi[B_*E_*T_];      // Z (proj input) hi, flat [4096][1024]
__device__ __nv_bfloat16 g_zlo[B_*E_*T_];
__device__ __nv_bfloat16 g_whi[E_*E_];         // Wr hi
__device__ __nv_bfloat16 g_wlo[E_*E_];

// ===========================================================================
// mma.sync / ldmatrix / cp.async helpers
// ===========================================================================
__device__ __forceinline__ uint32_t smem_u32(const void* p) {
    uint32_t a;
    asm("{ .reg .u64 t; cvta.to.shared.u64 t, %1; cvt.u32.u64 %0, t; }"
        : "=r"(a) : "l"(p));
    return a;
}
__device__ __forceinline__ void ldsm4(uint32_t* r, uint32_t addr) {
    asm volatile("ldmatrix.sync.aligned.m8n8.x4.shared.b16 {%0,%1,%2,%3}, [%4];"
                 : "=r"(r[0]), "=r"(r[1]), "=r"(r[2]), "=r"(r[3]) : "r"(addr));
}
__device__ __forceinline__ void ldsm4t(uint32_t* r, uint32_t addr) {
    asm volatile("ldmatrix.sync.aligned.m8n8.x4.trans.shared.b16 {%0,%1,%2,%3}, [%4];"
                 : "=r"(r[0]), "=r"(r[1]), "=r"(r[2]), "=r"(r[3]) : "r"(addr));
}
__device__ __forceinline__ void mma_bf16(float* c, const uint32_t* a, const uint32_t* b) {
    asm volatile(
        "mma.sync.aligned.m16n8k16.row.col.f32.bf16.bf16.f32 "
        "{%0,%1,%2,%3}, {%4,%5,%6,%7}, {%8,%9}, {%0,%1,%2,%3};"
        : "+f"(c[0]), "+f"(c[1]), "+f"(c[2]), "+f"(c[3])
        : "r"(a[0]), "r"(a[1]), "r"(a[2]), "r"(a[3]), "r"(b[0]), "r"(b[1]));
}
__device__ __forceinline__ void cpa16(uint32_t dst, const void* src) {
    asm volatile("cp.async.cg.shared.global [%0], [%1], 16;" :: "r"(dst), "l"(src));
}
__device__ __forceinline__ float fexp2(float x) {
    float y; asm("ex2.approx.ftz.f32 %0, %1;" : "=f"(y) : "f"(x)); return y;
}
__device__ __forceinline__ uint32_t pack_bf2(float x, float y) {
    __nv_bfloat16 hx = __float2bfloat16(x), hy = __float2bfloat16(y);
    return (uint32_t)__bfloat16_as_ushort(hx) |
           ((uint32_t)__bfloat16_as_ushort(hy) << 16);
}
// split two floats -> hi-packed u32 + lo-packed u32
__device__ __forceinline__ void split2(float a, float b, uint32_t& hi, uint32_t& lo) {
    __nv_bfloat16 h0 = __float2bfloat16(a), h1 = __float2bfloat16(b);
    hi = (uint32_t)__bfloat16_as_ushort(h0) | ((uint32_t)__bfloat16_as_ushort(h1) << 16);
    lo = pack_bf2(a - __bfloat162float(h0), b - __bfloat162float(h1));
}

// ---------------------------------------------------------------------------
// Kernel 1: QKV projections on mma.sync (3-term bf16 split).
// Issue order interleaved across accumulators (latency hiding);
// per-accumulator term order preserved (bitwise identical).
// ---------------------------------------------------------------------------
__global__ __launch_bounds__(256) void qkv_mma_kernel(
    const float* __restrict__ x,   // [T,B,E]
    const float* __restrict__ Wq,  // [H,S,S]
    const float* __restrict__ Wk,
    const float* __restrict__ Wv,
    const float* __restrict__ Er)  // [S,T]
{
    extern __shared__ __align__(16) char qsmem[];
    const uint32_t sb = smem_u32(qsmem);
    const int tid = threadIdx.x, wid = tid >> 5, lane = tid & 31;
    const int h = blockIdx.y, b = blockIdx.z;
    const int t0 = blockIdx.x * 128;

    // ---- load + split x tile [128][64] ----
    {
        const int r  = tid >> 1;
        const int d0 = (tid & 1) * 32;
        #pragma unroll
        for (int q = 0; q < 8; q++) {
            float4 v4 = *(const float4*)&x[(size_t)(t0 + r)*(B_*E_) + b*E_ + h*S_ + d0 + q*4];
            uint32_t h0, l0, h1, l1;
            split2(v4.x, v4.y, h0, l0);
            split2(v4.z, v4.w, h1, l1);
            uint32_t off = (uint32_t)r*144 + (uint32_t)(d0 + q*4)*2;
            *(uint2*)(qsmem + off)          = make_uint2(h0, h1);
            *(uint2*)(qsmem + 18432 + off)  = make_uint2(l0, l1);
        }
    }
    // ---- load + split W tiles [64][64] x 3 ----
    {
        const float* W[3] = { Wq + h*4096, Wk + h*4096, Wv + h*4096 };
        const int dd = tid >> 2;
        const int s0 = (tid & 3) * 16;
        #pragma unroll
        for (int w = 0; w < 3; w++) {
            uint32_t basew = 36864 + (uint32_t)w*18432;
            #pragma unroll
            for (int q = 0; q < 4; q++) {
                float4 w4 = *(const float4*)&W[w][dd*64 + s0 + q*4];
                uint32_t h0, l0, h1, l1;
                split2(w4.x, w4.y, h0, l0);
                split2(w4.z, w4.w, h1, l1);
                uint32_t off = (uint32_t)dd*144 + (uint32_t)(s0 + q*4)*2;
                *(uint2*)(qsmem + basew + off)         = make_uint2(h0, h1);
                *(uint2*)(qsmem + basew + 9216 + off)  = make_uint2(l0, l1);
            }
        }
    }
    __syncthreads();

    // ---- hoist A (x) fragments ----
    const uint32_t aoff = (uint32_t)(wid*16 + (lane & 15))*144 + ((lane >> 4) * 16);
    uint32_t axh[4][4], axl[4][4];
    #pragma unroll
    for (int ks = 0; ks < 4; ks++) {
        ldsm4(axh[ks], sb + aoff + ks*32);
        ldsm4(axl[ks], sb + 18432 + aoff + ks*32);
    }

    const uint32_t koff4 = (uint32_t)((lane & 7) + ((lane >> 4) << 3))*144 + (((lane >> 3) & 1) << 4);
    const size_t base = (size_t)(b*H_ + h) * T_ + t0;
    const int g = lane >> 2, tg = lane & 3;

    #pragma unroll
    for (int w = 0; w < 3; w++) {
        const uint32_t wbh = sb + 36864 + (uint32_t)w*18432;
        float sc[8][4];
        #pragma unroll
        for (int nf = 0; nf < 8; nf++)
            #pragma unroll
            for (int r = 0; r < 4; r++) sc[nf][r] = 0.0f;

        #pragma unroll
        for (int ks = 0; ks < 4; ks++) {
            #pragma unroll
            for (int pp = 0; pp < 4; pp += 2) {
                uint32_t bh4[2][4], bl4[2][4];
                #pragma unroll
                for (int i = 0; i < 2; i++) {
                    uint32_t ka = wbh + (uint32_t)(pp+i)*2304 + koff4 + ks*32;
                    ldsm4(bh4[i], ka);
                    ldsm4(bl4[i], ka + 9216);
                }
                // term hh
                #pragma unroll
                for (int i = 0; i < 2; i++) {
                    mma_bf16(sc[2*(pp+i)],   axh[ks], bh4[i]);
                    mma_bf16(sc[2*(pp+i)+1], axh[ks], bh4[i] + 2);
                }
                // term hl
                #pragma unroll
                for (int i = 0; i < 2; i++) {
                    mma_bf16(sc[2*(pp+i)],   axh[ks], bl4[i]);
                    mma_bf16(sc[2*(pp+i)+1], axh[ks], bl4[i] + 2);
                }
                // term lh
                #pragma unroll
                for (int i = 0; i < 2; i++) {
                    mma_bf16(sc[2*(pp+i)],   axl[ks], bh4[i]);
                    mma_bf16(sc[2*(pp+i)+1], axl[ks], bh4[i] + 2);
                }
            }
        }

        // ---- epilogue ----
        __nv_bfloat16* Ghi = (w == 0) ? g_qhi : (w == 1) ? g_khi : g_vhi;
        __nv_bfloat16* Glo = (w == 0) ? g_qlo : (w == 1) ? g_klo : g_vlo;
        #pragma unroll
        for (int nf = 0; nf < 8; nf++) {
            const int col = nf*8 + tg*2;
            #pragma unroll
            for (int h2 = 0; h2 < 2; h2++) {
                const int row = wid*16 + g + h2*8;
                float c0 = sc[nf][2*h2], c1 = sc[nf][2*h2+1];
                if (w == 1) {
                    int t = t0 + row;
                    c0 = (c0*(1.0f/32.0f) + Er[(size_t)col*T_ + t]) * LOG2E_;
                    c1 = (c1*(1.0f/32.0f) + Er[(size_t)(col+1)*T_ + t]) * LOG2E_;
                }
                uint32_t hi, lo;
                split2(c0, c1, hi, lo);
                size_t idx = (base + row)*S_ + col;
                *(uint32_t*)&Ghi[idx] = hi;
                *(uint32_t*)&Glo[idx] = lo;
            }
        }
    }
}

// ---------------------------------------------------------------------------
// Kernel 2: flash attention on mma.sync. BM=128, BN=64, D=64, 8 warps.
// 2-stage cp.async pipeline, Q-hi hoisted, p/np pairs interleaved across
// accumulators for mma latency hiding (term order per-acc preserved).
// smem: Qh 0, Ql 18432, 2 bufs at 36864 + s*36864. Total 110592 B.
// ---------------------------------------------------------------------------
__global__ __launch_bounds__(256, 2) void attn_mma_kernel()
{
    extern __shared__ __align__(16) char asmem[];
    const uint32_t sb = smem_u32(asmem);
    const int tid = threadIdx.x, wid = tid >> 5, lane = tid & 31;
    const int qi = (int)gridDim.x - 1 - (int)blockIdx.x;   // big tiles first
    const int bh = blockIdx.y, t0 = qi * 128;

    const __nv_bfloat16* qh = g_qhi + (size_t)bh*T_*S_;
    const __nv_bfloat16* ql = g_qlo + (size_t)bh*T_*S_;
    const __nv_bfloat16* kh = g_khi + (size_t)bh*T_*S_;
    const __nv_bfloat16* kl = g_klo + (size_t)bh*T_*S_;
    const __nv_bfloat16* vh = g_vhi + (size_t)bh*T_*S_;
    const __nv_bfloat16* vl = g_vlo + (size_t)bh*T_*S_;

    // group: Q (hi+lo)
    #pragma unroll
    for (int it = 0; it < 4; it++) {
        int idx = it*256 + tid, row = idx >> 3, ch = idx & 7;
        uint32_t so = (uint32_t)row*144 + ch*16;
        size_t go = (size_t)(t0 + row)*64 + ch*8;
        cpa16(sb + so, qh + go);
        cpa16(sb + 18432 + so, ql + go);
    }
    asm volatile("cp.async.commit_group;" ::: "memory");

#define APREF(jj, bb) do {                                                      \
        uint32_t base_ = sb + 36864 + (uint32_t)(bb)*36864;                     \
        _Pragma("unroll")                                                       \
        for (int it_ = 0; it_ < 2; it_++) {                                     \
            int idx_ = it_*256 + tid, row_ = idx_ >> 3, ch_ = idx_ & 7;         \
            uint32_t so_ = (uint32_t)row_*144 + ch_*16;                         \
            size_t go_ = (size_t)((jj)*64 + row_)*64 + ch_*8;                   \
            cpa16(base_ + so_,         kh + go_);                               \
            cpa16(base_ + 9216  + so_, kl + go_);                               \
            cpa16(base_ + 18432 + so_, vh + go_);                               \
            cpa16(base_ + 27648 + so_, vl + go_);                               \
        }                                                                       \
        asm volatile("cp.async.commit_group;" ::: "memory");                    \
    } while (0)

    const int jmax = 2*qi + 1;
    APREF(0, 0);

    // wait Q (allow K/V group 0 to stay in flight), hoist Q-hi fragments only
    asm volatile("cp.async.wait_group 1;" ::: "memory");
    __syncthreads();
    const uint32_t qoff = (uint32_t)(wid*16 + (lane & 15))*144 + ((lane >> 4) * 16);
    uint32_t aqh[4][4];
    #pragma unroll
    for (int ks = 0; ks < 4; ks++)
        ldsm4(aqh[ks], sb + qoff + ks*32);

    const uint32_t koff4 = (uint32_t)((lane & 7) + ((lane >> 4) << 3))*144 + (((lane >> 3) & 1) << 4);
    const uint32_t voff = (uint32_t)(((lane >> 3) & 1)*8 + (lane & 7))*144 + ((lane >> 4) * 16);

    float m0 = -1e30f, m1 = -1e30f, l0 = 0.0f, l1 = 0.0f;
    float o[8][4];
    #pragma unroll
    for (int nf = 0; nf < 8; nf++)
        #pragma unroll
        for (int r = 0; r < 4; r++) o[nf][r] = 0.0f;

    for (int j = 0; j <= jmax; j++) {
        const int buf = j & 1;
        if (j < jmax) {
            APREF(j + 1, buf ^ 1);
            asm volatile("cp.async.wait_group 1;" ::: "memory");
        } else {
            asm volatile("cp.async.wait_group 0;" ::: "memory");
        }
        __syncthreads();

        const uint32_t kbb = sb + 36864 + (uint32_t)buf*36864;
        const uint32_t vbb = kbb + 18432;

        // ---- S = Q @ K2^T (3-term split; p-pairs interleaved) ----
        float sc[8][4];
        #pragma unroll
        for (int nf = 0; nf < 8; nf++)
            #pragma unroll
            for (int r = 0; r < 4; r++) sc[nf][r] = 0.0f;

        #pragma unroll
        for (int ks = 0; ks < 4; ks++) {
            uint32_t aql[4];
            ldsm4(aql, sb + 18432 + qoff + ks*32);
            #pragma unroll
            for (int pp = 0; pp < 4; pp += 2) {
                uint32_t bh4[2][4], bl4[2][4];
                #pragma unroll
                for (int i = 0; i < 2; i++) {
                    uint32_t ka = kbb + (uint32_t)(pp+i)*2304 + koff4 + ks*32;
                    ldsm4(bh4[i], ka);
                    ldsm4(bl4[i], ka + 9216);
                }
                #pragma unroll
                for (int i = 0; i < 2; i++) {
                    mma_bf16(sc[2*(pp+i)],   aqh[ks], bh4[i]);
                    mma_bf16(sc[2*(pp+i)+1], aqh[ks], bh4[i] + 2);
                }
                #pragma unroll
                for (int i = 0; i < 2; i++) {
                    mma_bf16(sc[2*(pp+i)],   aqh[ks], bl4[i]);
                    mma_bf16(sc[2*(pp+i)+1], aqh[ks], bl4[i] + 2);
                }
                #pragma unroll
                for (int i = 0; i < 2; i++) {
                    mma_bf16(sc[2*(pp+i)],   aql, bh4[i]);
                    mma_bf16(sc[2*(pp+i)+1], aql, bh4[i] + 2);
                }
            }
        }

        // ---- causal mask (diagonal-straddling tiles only) ----
        if (j >= 2*qi) {
            const int rb = t0 + wid*16 + (lane >> 2);
            const int cb = j*64 + (lane & 3)*2;
            #pragma unroll
            for (int nf = 0; nf < 8; nf++) {
                int c = cb + nf*8;
                if (c     > rb)     sc[nf][0] = -1e30f;
                if (c + 1 > rb)     sc[nf][1] = -1e30f;
                if (c     > rb + 8) sc[nf][2] = -1e30f;
                if (c + 1 > rb + 8) sc[nf][3] = -1e30f;
            }
        }

        // ---- online softmax (base-2; log2e folded into k2) ----
        float rm0 = -1e30f, rm1 = -1e30f;
        #pragma unroll
        for (int nf = 0; nf < 8; nf++) {
            rm0 = fmaxf(rm0, fmaxf(sc[nf][0], sc[nf][1]));
            rm1 = fmaxf(rm1, fmaxf(sc[nf][2], sc[nf][3]));
        }
        rm0 = fmaxf(rm0, __shfl_xor_sync(0xffffffffu, rm0, 1));
        rm0 = fmaxf(rm0, __shfl_xor_sync(0xffffffffu, rm0, 2));
        rm1 = fmaxf(rm1, __shfl_xor_sync(0xffffffffu, rm1, 1));
        rm1 = fmaxf(rm1, __shfl_xor_sync(0xffffffffu, rm1, 2));
        float mn0 = fmaxf(m0, rm0), mn1 = fmaxf(m1, rm1);
        float a0 = fexp2(m0 - mn0), a1 = fexp2(m1 - mn1);
        m0 = mn0; m1 = mn1;

        float rs0 = 0.0f, rs1 = 0.0f;
        #pragma unroll
        for (int nf = 0; nf < 8; nf++) {
            sc[nf][0] = fexp2(sc[nf][0] - mn0);
            sc[nf][1] = fexp2(sc[nf][1] - mn0);
            sc[nf][2] = fexp2(sc[nf][2] - mn1);
            sc[nf][3] = fexp2(sc[nf][3] - mn1);
            rs0 += sc[nf][0] + sc[nf][1];
            rs1 += sc[nf][2] + sc[nf][3];
        }
        rs0 += __shfl_xor_sync(0xffffffffu, rs0, 1);
        rs0 += __shfl_xor_sync(0xffffffffu, rs0, 2);
        rs1 += __shfl_xor_sync(0xffffffffu, rs1, 1);
        rs1 += __shfl_xor_sync(0xffffffffu, rs1, 2);
        l0 = l0*a0 + rs0;
        l1 = l1*a1 + rs1;
        #pragma unroll
        for (int nf = 0; nf < 8; nf++) {
            o[nf][0] *= a0; o[nf][1] *= a0;
            o[nf][2] *= a1; o[nf][3] *= a1;
        }

        // ---- pack P fragments (C frag pairs -> A frags), hi/lo split ----
        uint32_t ph[4][4], pl[4][4];
        #pragma unroll
        for (int kb = 0; kb < 4; kb++) {
            const float* s0 = sc[2*kb];
            const float* s1 = sc[2*kb+1];
            float rr[8] = {s0[0], s0[1], s0[2], s0[3], s1[0], s1[1], s1[2], s1[3]};
            #pragma unroll
            for (int q2 = 0; q2 < 4; q2++)
                split2(rr[q2*2], rr[q2*2+1], ph[kb][q2], pl[kb][q2]);
        }

        // ---- O += P @ V (3-term split; np-pairs interleaved) ----
        #pragma unroll
        for (int kb = 0; kb < 4; kb++) {
            #pragma unroll
            for (int npp = 0; npp < 4; npp += 2) {
                uint32_t v4h[2][4], v4l[2][4];
                #pragma unroll
                for (int i = 0; i < 2; i++) {
                    uint32_t va = vbb + (uint32_t)kb*2304 + voff + (npp+i)*32;
                    ldsm4t(v4h[i], va);
                    ldsm4t(v4l[i], va + 9216);
                }
                #pragma unroll
                for (int i = 0; i < 2; i++) {
                    mma_bf16(o[2*(npp+i)],   ph[kb], v4h[i]);
                    mma_bf16(o[2*(npp+i)+1], ph[kb], v4h[i] + 2);
                }
                #pragma unroll
                for (int i = 0; i < 2; i++) {
                    mma_bf16(o[2*(npp+i)],   ph[kb], v4l[i]);
                    mma_bf16(o[2*(npp+i)+1], ph[kb], v4l[i] + 2);
                }
                #pragma unroll
                for (int i = 0; i < 2; i++) {
                    mma_bf16(o[2*(npp+i)],   pl[kb], v4h[i]);
                    mma_bf16(o[2*(npp+i)+1], pl[kb], v4h[i] + 2);
                }
            }
        }
        __syncthreads();   // protect buffer reuse by next iteration's APREF
    }

    // ---- epilogue: normalize, stage [d][t] in smem, write Z hi/lo e-major ----
    float* stage = (float*)(asmem + 36864);   // [64][132] floats
    {
        float inv0 = 1.0f / l0, inv1 = 1.0f / l1;
        const int g = lane >> 2, tg = lane & 3;
        const int tl = wid*16 + g;
        #pragma unroll
        for (int nf = 0; nf < 8; nf++) {
            int d = nf*8 + tg*2;
            stage[d*132 + tl]           = o[nf][0] * inv0;
            stage[(d+1)*132 + tl]       = o[nf][1] * inv0;
            stage[d*132 + tl + 8]       = o[nf][2] * inv1;
            stage[(d+1)*132 + tl + 8]   = o[nf][3] * inv1;
        }
    }
    __syncthreads();

    const int b = bh >> 4, h = bh & 15;
    const size_t basez = ((size_t)b*E_ + h*S_) * T_;
    #pragma unroll
    for (int it = 0; it < 32; it++) {
        int idx = it*256 + tid;
        int d = idx >> 7, t = idx & 127;
        float y = stage[d*132 + t];
        __nv_bfloat16 hi = __float2bfloat16(y);
        size_t off = basez + (size_t)d*T_ + t0 + t;
        g_zhi[off] = hi;
        g_zlo[off] = __float2bfloat16(y - __bfloat162float(hi));
    }
}

// ---------------------------------------------------------------------------
// Kernel 3a: Wr -> bf16 hi/lo split
// ---------------------------------------------------------------------------
__global__ __launch_bounds__(256) void wconv_kernel(const float* __restrict__ Wr)
{
    size_t i = ((size_t)blockIdx.x*256 + threadIdx.x) * 4;
    float4 w = *(const float4*)&Wr[i];
    float v[4] = {w.x, w.y, w.z, w.w};
    #pragma unroll
    for (int q = 0; q < 4; q++) {
        __nv_bfloat16 hi = __float2bfloat16(v[q]);
        g_whi[i+q] = hi;
        g_wlo[i+q] = __float2bfloat16(v[q] - __bfloat162float(hi));
    }
}

// ---------------------------------------------------------------------------
// Kernel 3b: output projection via mma.sync (bf16, 3-term split).
// 128x128 CTA tile, 4 warps of 64x64. All fragments loaded per ks, then
// issue order term -> p -> mf (dependent-reuse distance 16).
// ---------------------------------------------------------------------------
#define PTILE_ (128*80)
#define PBUF_  (4*PTILE_)
__global__ __launch_bounds__(128) void proj_mma_kernel(
    const float* __restrict__ br, float* __restrict__ out)
{
    extern __shared__ __align__(128) char ps[];
    const uint32_t sb = smem_u32(ps);
    const int tid = threadIdx.x, wid = tid >> 5, lane = tid & 31;
    const int n0 = blockIdx.x * 128, m0 = blockIdx.y * 128;
    const int wm = wid >> 1, wn = wid & 1;

    float acc[4][8][4];
    #pragma unroll
    for (int mf = 0; mf < 4; mf++)
        #pragma unroll
        for (int nf = 0; nf < 8; nf++)
            #pragma unroll
            for (int r = 0; r < 4; r++) acc[mf][nf][r] = 0.0f;

    #define ISSUE(cc, bb) do {                                                  \
        const int k0i = (cc) * 32;                                              \
        uint32_t base = sb + (bb) * PBUF_;                                      \
        _Pragma("unroll")                                                       \
        for (int q = 0; q < 4; q++) {                                           \
            int row = (tid >> 2) + q*32;                                        \
            uint32_t soff = (uint32_t)row*80 + (uint32_t)(tid & 3)*16;          \
            size_t ga = (size_t)(m0 + row)*E_ + k0i + (tid & 3)*8;              \
            size_t gb = (size_t)(n0 + row)*E_ + k0i + (tid & 3)*8;              \
            cpa16(base + 0*PTILE_ + soff, g_zhi + ga);                          \
            cpa16(base + 1*PTILE_ + soff, g_zlo + ga);                          \
            cpa16(base + 2*PTILE_ + soff, g_whi + gb);                          \
            cpa16(base + 3*PTILE_ + soff, g_wlo + gb);                          \
        }                                                                       \
        asm volatile("cp.async.commit_group;" ::: "memory");                    \
    } while (0)

    const uint32_t koff4p = (uint32_t)((lane & 7) + ((lane >> 4) << 3))*80 + (((lane >> 3) & 1) << 4);
    const int am = lane & 15;

    ISSUE(0, 0);
    for (int c = 0; c < 32; c++) {
        const int buf = c & 1;
        if (c + 1 < 32) {
            ISSUE(c + 1, buf ^ 1);
            asm volatile("cp.async.wait_group 1;" ::: "memory");
        } else {
            asm volatile("cp.async.wait_group 0;" ::: "memory");
        }
        __syncthreads();

        const uint32_t Ah = sb + buf*PBUF_;
        const uint32_t Al = Ah + PTILE_;
        const uint32_t Bh = Ah + 2*PTILE_;
        const uint32_t Bl = Ah + 3*PTILE_;

        #pragma unroll
        for (int ks = 0; ks < 2; ks++) {
            uint32_t ah[4][4], al[4][4], bh4[4][4], bl4[4][4];
            const uint32_t akoff = (uint32_t)(ks*32 + (lane >> 4)*16);
            #pragma unroll
            for (int mf = 0; mf < 4; mf++) {
                uint32_t ro = (uint32_t)(wm*64 + mf*16 + am)*80 + akoff;
                ldsm4(ah[mf], Ah + ro);
                ldsm4(al[mf], Al + ro);
            }
            #pragma unroll
            for (int p = 0; p < 4; p++) {
                uint32_t ro = (uint32_t)(wn*64 + p*16)*80 + koff4p + ks*32;
                ldsm4(bh4[p], Bh + ro);
                ldsm4(bl4[p], Bl + ro);
            }
            // term hh: acc[mf][2p] += ah*bh (distance 16 between reuses)
            #pragma unroll
            for (int p = 0; p < 4; p++)
                #pragma unroll
                for (int mf = 0; mf < 4; mf++) {
                    mma_bf16(acc[mf][2*p],   ah[mf], bh4[p]);
                    mma_bf16(acc[mf][2*p+1], ah[mf], bh4[p] + 2);
                }
            // term hl
            #pragma unroll
            for (int p = 0; p < 4; p++)
                #pragma unroll
                for (int mf = 0; mf < 4; mf++) {
                    mma_bf16(acc[mf][2*p],   ah[mf], bl4[p]);
                    mma_bf16(acc[mf][2*p+1], ah[mf], bl4[p] + 2);
                }
            // term lh
            #pragma unroll
            for (int p = 0; p < 4; p++)
                #pragma unroll
                for (int mf = 0; mf < 4; mf++) {
                    mma_bf16(acc[mf][2*p],   al[mf], bh4[p]);
                    mma_bf16(acc[mf][2*p+1], al[mf], bh4[p] + 2);
                }
        }
        __syncthreads();
    }

    const int g = lane >> 2, tg = lane & 3;
    #pragma unroll
    for (int nf = 0; nf < 8; nf++) {
        const int col = n0 + wn*64 + nf*8 + tg*2;
        float2 bb = *(const float2*)&br[col];
        #pragma unroll
        for (int mf = 0; mf < 4; mf++) {
            const int row = m0 + wm*64 + mf*16 + g;
            float2 v0 = make_float2(acc[mf][nf][0] + bb.x, acc[mf][nf][1] + bb.y);
            float2 v1 = make_float2(acc[mf][nf][2] + bb.x, acc[mf][nf][3] + bb.y);
            *(float2*)&out[(size_t)row*E_ + col]       = v0;
            *(float2*)&out[(size_t)(row + 8)*E_ + col] = v1;
        }
    }
}

// ---------------------------------------------------------------------------
extern "C" void kernel_launch(void* const* d_in, const int* in_sizes, int n_in,
                              void* d_out, int out_size)
{
    const float* x  = (const float*)d_in[0];
    const float* Wq = (const float*)d_in[1];
    const float* Wk = (const float*)d_in[2];
    const float* Wv = (const float*)d_in[3];
    const float* Er = (const float*)d_in[4];
    const float* Wr = (const float*)d_in[5];
    const float* br = (const float*)d_in[6];
    float* out = (float*)d_out;

    const int smem_qkv = 92160;
    cudaFuncSetAttribute(qkv_mma_kernel,
                         cudaFuncAttributeMaxDynamicSharedMemorySize, smem_qkv);
    qkv_mma_kernel<<<dim3(T_/128, H_, B_), 256, smem_qkv>>>(x, Wq, Wk, Wv, Er);

    wconv_kernel<<<(E_*E_)/(256*4), 256>>>(Wr);

    const int smem_attn = 110592;   // 2-stage; 2 CTAs/SM
    cudaFuncSetAttribute(attn_mma_kernel,
                         cudaFuncAttributeMaxDynamicSharedMemorySize, smem_attn);
    attn_mma_kernel<<<dim3(T_/128, BH_), 256, smem_attn>>>();

    const int smem_proj = 2 * PBUF_;  // 81920; 2 CTAs/SM
    cudaFuncSetAttribute(proj_mma_kernel,
                         cudaFuncAttributeMaxDynamicSharedMemorySize, smem_proj);
    proj_mma_kernel<<<dim3(E_/128, (B_*T_)/128), 128, smem_proj>>>(br, out);
}

// round 16
// speedup vs baseline: 1.2494x; 1.1657x over previous
#include <cuda_runtime.h>
#include <cuda_bf16.h>
#include <cuda_fp16.h>
#include <math.h>
#include <stdint.h>

#define T_ 2048
#define B_ 2
#define E_ 1024
#define H_ 16
#define S_ 64
#define BH_ (B_*H_)
#define LOG2E_ 1.4426950408889634f

// Scratch (static device globals; allocation-free per harness rules)
__device__ __nv_bfloat16 g_qhi[B_*H_*T_*S_];   // [bh][t][d] q hi (bf16)
__device__ __nv_bfloat16 g_qlo[B_*H_*T_*S_];
__device__ __nv_bfloat16 g_khi[B_*H_*T_*S_];   // [bh][r][d] k2 = (k/32 + Er)*log2e
__device__ __nv_bfloat16 g_klo[B_*H_*T_*S_];
__device__ __half        g_v16[B_*H_*T_*S_];   // [bh][r][d] v single f16
__device__ __half        g_zh16[B_*E_*T_];     // Z hi (f16 split), flat [4096][1024]
__device__ __half        g_zl16[B_*E_*T_];     // Z lo
__device__ __half        g_w16 [E_*E_];        // Wr single f16

// ===========================================================================
// mma.sync / ldmatrix / cp.async helpers
// ===========================================================================
__device__ __forceinline__ uint32_t smem_u32(const void* p) {
    uint32_t a;
    asm("{ .reg .u64 t; cvta.to.shared.u64 t, %1; cvt.u32.u64 %0, t; }"
        : "=r"(a) : "l"(p));
    return a;
}
__device__ __forceinline__ void ldsm4(uint32_t* r, uint32_t addr) {
    asm volatile("ldmatrix.sync.aligned.m8n8.x4.shared.b16 {%0,%1,%2,%3}, [%4];"
                 : "=r"(r[0]), "=r"(r[1]), "=r"(r[2]), "=r"(r[3]) : "r"(addr));
}
__device__ __forceinline__ void ldsm4t(uint32_t* r, uint32_t addr) {
    asm volatile("ldmatrix.sync.aligned.m8n8.x4.trans.shared.b16 {%0,%1,%2,%3}, [%4];"
                 : "=r"(r[0]), "=r"(r[1]), "=r"(r[2]), "=r"(r[3]) : "r"(addr));
}
__device__ __forceinline__ void mma_bf16(float* c, const uint32_t* a, const uint32_t* b) {
    asm volatile(
        "mma.sync.aligned.m16n8k16.row.col.f32.bf16.bf16.f32 "
        "{%0,%1,%2,%3}, {%4,%5,%6,%7}, {%8,%9}, {%0,%1,%2,%3};"
        : "+f"(c[0]), "+f"(c[1]), "+f"(c[2]), "+f"(c[3])
        : "r"(a[0]), "r"(a[1]), "r"(a[2]), "r"(a[3]), "r"(b[0]), "r"(b[1]));
}
__device__ __forceinline__ void mma_f16(float* c, const uint32_t* a, const uint32_t* b) {
    asm volatile(
        "mma.sync.aligned.m16n8k16.row.col.f32.f16.f16.f32 "
        "{%0,%1,%2,%3}, {%4,%5,%6,%7}, {%8,%9}, {%0,%1,%2,%3};"
        : "+f"(c[0]), "+f"(c[1]), "+f"(c[2]), "+f"(c[3])
        : "r"(a[0]), "r"(a[1]), "r"(a[2]), "r"(a[3]), "r"(b[0]), "r"(b[1]));
}
__device__ __forceinline__ void cpa16(uint32_t dst, const void* src) {
    asm volatile("cp.async.cg.shared.global [%0], [%1], 16;" :: "r"(dst), "l"(src));
}
__device__ __forceinline__ float fexp2(float x) {
    float y; asm("ex2.approx.ftz.f32 %0, %1;" : "=f"(y) : "f"(x)); return y;
}
__device__ __forceinline__ uint32_t pack_bf2(float x, float y) {
    __nv_bfloat16 hx = __float2bfloat16(x), hy = __float2bfloat16(y);
    return (uint32_t)__bfloat16_as_ushort(hx) |
           ((uint32_t)__bfloat16_as_ushort(hy) << 16);
}
__device__ __forceinline__ void split2(float a, float b, uint32_t& hi, uint32_t& lo) {
    __nv_bfloat16 h0 = __float2bfloat16(a), h1 = __float2bfloat16(b);
    hi = (uint32_t)__bfloat16_as_ushort(h0) | ((uint32_t)__bfloat16_as_ushort(h1) << 16);
    lo = pack_bf2(a - __bfloat162float(h0), b - __bfloat162float(h1));
}
__device__ __forceinline__ uint32_t pack_h2(float x, float y) {
    __half hx = __float2half_rn(x), hy = __float2half_rn(y);
    return (uint32_t)__half_as_ushort(hx) |
           ((uint32_t)__half_as_ushort(hy) << 16);
}
// f16 split of two floats -> hi-packed u32 + lo-packed u32 (a = hi + lo exact)
__device__ __forceinline__ void split2h(float a, float b, uint32_t& hi, uint32_t& lo) {
    __half h0 = __float2half_rn(a), h1 = __float2half_rn(b);
    hi = (uint32_t)__half_as_ushort(h0) | ((uint32_t)__half_as_ushort(h1) << 16);
    lo = pack_h2(a - __half2float(h0), b - __half2float(h1));
}

// ---------------------------------------------------------------------------
// Kernel 1: QKV projections on mma.sync (3-term bf16 split compute).
// q,k2 stored bf16 hi/lo; v stored single f16.
// ---------------------------------------------------------------------------
__global__ __launch_bounds__(256) void qkv_mma_kernel(
    const float* __restrict__ x,   // [T,B,E]
    const float* __restrict__ Wq,  // [H,S,S]
    const float* __restrict__ Wk,
    const float* __restrict__ Wv,
    const float* __restrict__ Er)  // [S,T]
{
    extern __shared__ __align__(16) char qsmem[];
    const uint32_t sb = smem_u32(qsmem);
    const int tid = threadIdx.x, wid = tid >> 5, lane = tid & 31;
    const int h = blockIdx.y, b = blockIdx.z;
    const int t0 = blockIdx.x * 128;

    // ---- load + split x tile [128][64] (bf16 hi/lo) ----
    {
        const int r  = tid >> 1;
        const int d0 = (tid & 1) * 32;
        #pragma unroll
        for (int q = 0; q < 8; q++) {
            float4 v4 = *(const float4*)&x[(size_t)(t0 + r)*(B_*E_) + b*E_ + h*S_ + d0 + q*4];
            uint32_t h0, l0, h1, l1;
            split2(v4.x, v4.y, h0, l0);
            split2(v4.z, v4.w, h1, l1);
            uint32_t off = (uint32_t)r*144 + (uint32_t)(d0 + q*4)*2;
            *(uint2*)(qsmem + off)          = make_uint2(h0, h1);
            *(uint2*)(qsmem + 18432 + off)  = make_uint2(l0, l1);
        }
    }
    // ---- load + split W tiles [64][64] x 3 ----
    {
        const float* W[3] = { Wq + h*4096, Wk + h*4096, Wv + h*4096 };
        const int dd = tid >> 2;
        const int s0 = (tid & 3) * 16;
        #pragma unroll
        for (int w = 0; w < 3; w++) {
            uint32_t basew = 36864 + (uint32_t)w*18432;
            #pragma unroll
            for (int q = 0; q < 4; q++) {
                float4 w4 = *(const float4*)&W[w][dd*64 + s0 + q*4];
                uint32_t h0, l0, h1, l1;
                split2(w4.x, w4.y, h0, l0);
                split2(w4.z, w4.w, h1, l1);
                uint32_t off = (uint32_t)dd*144 + (uint32_t)(s0 + q*4)*2;
                *(uint2*)(qsmem + basew + off)         = make_uint2(h0, h1);
                *(uint2*)(qsmem + basew + 9216 + off)  = make_uint2(l0, l1);
            }
        }
    }
    __syncthreads();

    // ---- hoist A (x) fragments ----
    const uint32_t aoff = (uint32_t)(wid*16 + (lane & 15))*144 + ((lane >> 4) * 16);
    uint32_t axh[4][4], axl[4][4];
    #pragma unroll
    for (int ks = 0; ks < 4; ks++) {
        ldsm4(axh[ks], sb + aoff + ks*32);
        ldsm4(axl[ks], sb + 18432 + aoff + ks*32);
    }

    const uint32_t koff4 = (uint32_t)((lane & 7) + ((lane >> 4) << 3))*144 + (((lane >> 3) & 1) << 4);
    const size_t base = (size_t)(b*H_ + h) * T_ + t0;
    const int g = lane >> 2, tg = lane & 3;

    #pragma unroll
    for (int w = 0; w < 3; w++) {
        const uint32_t wbh = sb + 36864 + (uint32_t)w*18432;
        float sc[8][4];
        #pragma unroll
        for (int nf = 0; nf < 8; nf++)
            #pragma unroll
            for (int r = 0; r < 4; r++) sc[nf][r] = 0.0f;

        #pragma unroll
        for (int ks = 0; ks < 4; ks++) {
            #pragma unroll
            for (int pp = 0; pp < 4; pp += 2) {
                uint32_t bh4[2][4], bl4[2][4];
                #pragma unroll
                for (int i = 0; i < 2; i++) {
                    uint32_t ka = wbh + (uint32_t)(pp+i)*2304 + koff4 + ks*32;
                    ldsm4(bh4[i], ka);
                    ldsm4(bl4[i], ka + 9216);
                }
                #pragma unroll
                for (int i = 0; i < 2; i++) {
                    mma_bf16(sc[2*(pp+i)],   axh[ks], bh4[i]);
                    mma_bf16(sc[2*(pp+i)+1], axh[ks], bh4[i] + 2);
                }
                #pragma unroll
                for (int i = 0; i < 2; i++) {
                    mma_bf16(sc[2*(pp+i)],   axh[ks], bl4[i]);
                    mma_bf16(sc[2*(pp+i)+1], axh[ks], bl4[i] + 2);
                }
                #pragma unroll
                for (int i = 0; i < 2; i++) {
                    mma_bf16(sc[2*(pp+i)],   axl[ks], bh4[i]);
                    mma_bf16(sc[2*(pp+i)+1], axl[ks], bh4[i] + 2);
                }
            }
        }

        // ---- epilogue ----
        #pragma unroll
        for (int nf = 0; nf < 8; nf++) {
            const int col = nf*8 + tg*2;
            #pragma unroll
            for (int h2 = 0; h2 < 2; h2++) {
                const int row = wid*16 + g + h2*8;
                float c0 = sc[nf][2*h2], c1 = sc[nf][2*h2+1];
                size_t idx = (base + row)*S_ + col;
                if (w == 0) {
                    uint32_t hi, lo;
                    split2(c0, c1, hi, lo);
                    *(uint32_t*)&g_qhi[idx] = hi;
                    *(uint32_t*)&g_qlo[idx] = lo;
                } else if (w == 1) {
                    int t = t0 + row;
                    c0 = (c0*(1.0f/32.0f) + Er[(size_t)col*T_ + t]) * LOG2E_;
                    c1 = (c1*(1.0f/32.0f) + Er[(size_t)(col+1)*T_ + t]) * LOG2E_;
                    uint32_t hi, lo;
                    split2(c0, c1, hi, lo);
                    *(uint32_t*)&g_khi[idx] = hi;
                    *(uint32_t*)&g_klo[idx] = lo;
                } else {
                    *(uint32_t*)&g_v16[idx] = pack_h2(c0, c1);
                }
            }
        }
    }
}

// ---------------------------------------------------------------------------
// Kernel 2: flash attention. QK: bf16 3-term (unchanged). PV: f16 2-term
// (P split exact in f16, V single f16) -> 160 mma/iter (was 192).
// smem: Qh 0, Ql 18432, 2 bufs at 36864 + s*27648
//   (buf: Kh +0, Kl +9216, V16 +18432). Total 92160 B. 2 CTAs/SM.
// ---------------------------------------------------------------------------
__global__ __launch_bounds__(256, 2) void attn_mma_kernel()
{
    extern __shared__ __align__(16) char asmem[];
    const uint32_t sb = smem_u32(asmem);
    const int tid = threadIdx.x, wid = tid >> 5, lane = tid & 31;
    const int qi = (int)gridDim.x - 1 - (int)blockIdx.x;   // big tiles first
    const int bh = blockIdx.y, t0 = qi * 128;

    const __nv_bfloat16* qh = g_qhi + (size_t)bh*T_*S_;
    const __nv_bfloat16* ql = g_qlo + (size_t)bh*T_*S_;
    const __nv_bfloat16* kh = g_khi + (size_t)bh*T_*S_;
    const __nv_bfloat16* kl = g_klo + (size_t)bh*T_*S_;
    const __half*        vv = g_v16 + (size_t)bh*T_*S_;

    // group: Q (hi+lo)
    #pragma unroll
    for (int it = 0; it < 4; it++) {
        int idx = it*256 + tid, row = idx >> 3, ch = idx & 7;
        uint32_t so = (uint32_t)row*144 + ch*16;
        size_t go = (size_t)(t0 + row)*64 + ch*8;
        cpa16(sb + so, qh + go);
        cpa16(sb + 18432 + so, ql + go);
    }
    asm volatile("cp.async.commit_group;" ::: "memory");

#define APREF(jj, bb) do {                                                      \
        uint32_t base_ = sb + 36864 + (uint32_t)(bb)*27648;                     \
        _Pragma("unroll")                                                       \
        for (int it_ = 0; it_ < 2; it_++) {                                     \
            int idx_ = it_*256 + tid, row_ = idx_ >> 3, ch_ = idx_ & 7;         \
            uint32_t so_ = (uint32_t)row_*144 + ch_*16;                         \
            size_t go_ = (size_t)((jj)*64 + row_)*64 + ch_*8;                   \
            cpa16(base_ + so_,         kh + go_);                               \
            cpa16(base_ + 9216  + so_, kl + go_);                               \
            cpa16(base_ + 18432 + so_, vv + go_);                               \
        }                                                                       \
        asm volatile("cp.async.commit_group;" ::: "memory");                    \
    } while (0)

    const int jmax = 2*qi + 1;
    APREF(0, 0);

    // wait Q (allow K/V group 0 in flight), hoist Q-hi fragments only
    asm volatile("cp.async.wait_group 1;" ::: "memory");
    __syncthreads();
    const uint32_t qoff = (uint32_t)(wid*16 + (lane & 15))*144 + ((lane >> 4) * 16);
    uint32_t aqh[4][4];
    #pragma unroll
    for (int ks = 0; ks < 4; ks++)
        ldsm4(aqh[ks], sb + qoff + ks*32);

    const uint32_t koff4 = (uint32_t)((lane & 7) + ((lane >> 4) << 3))*144 + (((lane >> 3) & 1) << 4);
    const uint32_t voff = (uint32_t)(((lane >> 3) & 1)*8 + (lane & 7))*144 + ((lane >> 4) * 16);

    float m0 = -1e30f, m1 = -1e30f, l0 = 0.0f, l1 = 0.0f;
    float o[8][4];
    #pragma unroll
    for (int nf = 0; nf < 8; nf++)
        #pragma unroll
        for (int r = 0; r < 4; r++) o[nf][r] = 0.0f;

    for (int j = 0; j <= jmax; j++) {
        const int buf = j & 1;
        if (j < jmax) {
            APREF(j + 1, buf ^ 1);
            asm volatile("cp.async.wait_group 1;" ::: "memory");
        } else {
            asm volatile("cp.async.wait_group 0;" ::: "memory");
        }
        __syncthreads();

        const uint32_t kbb = sb + 36864 + (uint32_t)buf*27648;
        const uint32_t vbb = kbb + 18432;

        // ---- S = Q @ K2^T (bf16 3-term; p-pairs interleaved) ----
        float sc[8][4];
        #pragma unroll
        for (int nf = 0; nf < 8; nf++)
            #pragma unroll
            for (int r = 0; r < 4; r++) sc[nf][r] = 0.0f;

        #pragma unroll
        for (int ks = 0; ks < 4; ks++) {
            uint32_t aql[4];
            ldsm4(aql, sb + 18432 + qoff + ks*32);
            #pragma unroll
            for (int pp = 0; pp < 4; pp += 2) {
                uint32_t bh4[2][4], bl4[2][4];
                #pragma unroll
                for (int i = 0; i < 2; i++) {
                    uint32_t ka = kbb + (uint32_t)(pp+i)*2304 + koff4 + ks*32;
                    ldsm4(bh4[i], ka);
                    ldsm4(bl4[i], ka + 9216);
                }
                #pragma unroll
                for (int i = 0; i < 2; i++) {
                    mma_bf16(sc[2*(pp+i)],   aqh[ks], bh4[i]);
                    mma_bf16(sc[2*(pp+i)+1], aqh[ks], bh4[i] + 2);
                }
                #pragma unroll
                for (int i = 0; i < 2; i++) {
                    mma_bf16(sc[2*(pp+i)],   aqh[ks], bl4[i]);
                    mma_bf16(sc[2*(pp+i)+1], aqh[ks], bl4[i] + 2);
                }
                #pragma unroll
                for (int i = 0; i < 2; i++) {
                    mma_bf16(sc[2*(pp+i)],   aql, bh4[i]);
                    mma_bf16(sc[2*(pp+i)+1], aql, bh4[i] + 2);
                }
            }
        }

        // ---- causal mask (diagonal-straddling tiles only) ----
        if (j >= 2*qi) {
            const int rb = t0 + wid*16 + (lane >> 2);
            const int cb = j*64 + (lane & 3)*2;
            #pragma unroll
            for (int nf = 0; nf < 8; nf++) {
                int c = cb + nf*8;
                if (c     > rb)     sc[nf][0] = -1e30f;
                if (c + 1 > rb)     sc[nf][1] = -1e30f;
                if (c     > rb + 8) sc[nf][2] = -1e30f;
                if (c + 1 > rb + 8) sc[nf][3] = -1e30f;
            }
        }

        // ---- online softmax (base-2; log2e folded into k2) ----
        float rm0 = -1e30f, rm1 = -1e30f;
        #pragma unroll
        for (int nf = 0; nf < 8; nf++) {
            rm0 = fmaxf(rm0, fmaxf(sc[nf][0], sc[nf][1]));
            rm1 = fmaxf(rm1, fmaxf(sc[nf][2], sc[nf][3]));
        }
        rm0 = fmaxf(rm0, __shfl_xor_sync(0xffffffffu, rm0, 1));
        rm0 = fmaxf(rm0, __shfl_xor_sync(0xffffffffu, rm0, 2));
        rm1 = fmaxf(rm1, __shfl_xor_sync(0xffffffffu, rm1, 1));
        rm1 = fmaxf(rm1, __shfl_xor_sync(0xffffffffu, rm1, 2));
        float mn0 = fmaxf(m0, rm0), mn1 = fmaxf(m1, rm1);
        float a0 = fexp2(m0 - mn0), a1 = fexp2(m1 - mn1);
        m0 = mn0; m1 = mn1;

        float rs0 = 0.0f, rs1 = 0.0f;
        #pragma unroll
        for (int nf = 0; nf < 8; nf++) {
            sc[nf][0] = fexp2(sc[nf][0] - mn0);
            sc[nf][1] = fexp2(sc[nf][1] - mn0);
            sc[nf][2] = fexp2(sc[nf][2] - mn1);
            sc[nf][3] = fexp2(sc[nf][3] - mn1);
            rs0 += sc[nf][0] + sc[nf][1];
            rs1 += sc[nf][2] + sc[nf][3];
        }
        rs0 += __shfl_xor_sync(0xffffffffu, rs0, 1);
        rs0 += __shfl_xor_sync(0xffffffffu, rs0, 2);
        rs1 += __shfl_xor_sync(0xffffffffu, rs1, 1);
        rs1 += __shfl_xor_sync(0xffffffffu, rs1, 2);
        l0 = l0*a0 + rs0;
        l1 = l1*a1 + rs1;
        #pragma unroll
        for (int nf = 0; nf < 8; nf++) {
            o[nf][0] *= a0; o[nf][1] *= a0;
            o[nf][2] *= a1; o[nf][3] *= a1;
        }

        // ---- pack P fragments (f16 hi/lo split; exact to 2^-22) ----
        uint32_t ph[4][4], pl[4][4];
        #pragma unroll
        for (int kb = 0; kb < 4; kb++) {
            const float* s0 = sc[2*kb];
            const float* s1 = sc[2*kb+1];
            float rr[8] = {s0[0], s0[1], s0[2], s0[3], s1[0], s1[1], s1[2], s1[3]};
            #pragma unroll
            for (int q2 = 0; q2 < 4; q2++)
                split2h(rr[q2*2], rr[q2*2+1], ph[kb][q2], pl[kb][q2]);
        }

        // ---- O += P @ V (f16 2-term: ph*v + pl*v; V single) ----
        #pragma unroll
        for (int kb = 0; kb < 4; kb++) {
            #pragma unroll
            for (int npp = 0; npp < 4; npp += 2) {
                uint32_t v4[2][4];
                #pragma unroll
                for (int i = 0; i < 2; i++)
                    ldsm4t(v4[i], vbb + (uint32_t)kb*2304 + voff + (npp+i)*32);
                #pragma unroll
                for (int i = 0; i < 2; i++) {
                    mma_f16(o[2*(npp+i)],   ph[kb], v4[i]);
                    mma_f16(o[2*(npp+i)+1], ph[kb], v4[i] + 2);
                }
                #pragma unroll
                for (int i = 0; i < 2; i++) {
                    mma_f16(o[2*(npp+i)],   pl[kb], v4[i]);
                    mma_f16(o[2*(npp+i)+1], pl[kb], v4[i] + 2);
                }
            }
        }
        __syncthreads();   // protect buffer reuse by next iteration's APREF
    }

    // ---- epilogue: normalize, stage [d][t] in smem, write Z f16 hi/lo ----
    float* stage = (float*)(asmem + 36864);   // [64][132] floats
    {
        float inv0 = 1.0f / l0, inv1 = 1.0f / l1;
        const int g = lane >> 2, tg = lane & 3;
        const int tl = wid*16 + g;
        #pragma unroll
        for (int nf = 0; nf < 8; nf++) {
            int d = nf*8 + tg*2;
            stage[d*132 + tl]           = o[nf][0] * inv0;
            stage[(d+1)*132 + tl]       = o[nf][1] * inv0;
            stage[d*132 + tl + 8]       = o[nf][2] * inv1;
            stage[(d+1)*132 + tl + 8]   = o[nf][3] * inv1;
        }
    }
    __syncthreads();

    const int b = bh >> 4, h = bh & 15;
    const size_t basez = ((size_t)b*E_ + h*S_) * T_;
    #pragma unroll
    for (int it = 0; it < 32; it++) {
        int idx = it*256 + tid;
        int d = idx >> 7, t = idx & 127;
        float y = stage[d*132 + t];
        __half hi = __float2half_rn(y);
        size_t off = basez + (size_t)d*T_ + t0 + t;
        g_zh16[off] = hi;
        g_zl16[off] = __float2half_rn(y - __half2float(hi));
    }
}

// ---------------------------------------------------------------------------
// Kernel 3a: Wr -> single f16
// ---------------------------------------------------------------------------
__global__ __launch_bounds__(256) void wconv_kernel(const float* __restrict__ Wr)
{
    size_t i = ((size_t)blockIdx.x*256 + threadIdx.x) * 4;
    float4 w = *(const float4*)&Wr[i];
    uint2 u;
    u.x = pack_h2(w.x, w.y);
    u.y = pack_h2(w.z, w.w);
    *(uint2*)&g_w16[i] = u;
}

// ---------------------------------------------------------------------------
// Kernel 3b: output projection via mma.sync (f16 2-term: Z split, Wr single).
// 128x128 CTA tile, 4 warps of 64x64, 128 mma/chunk (was 192).
// ---------------------------------------------------------------------------
#define PTILE_ (128*80)
#define PBUF_  (3*PTILE_)
__global__ __launch_bounds__(128) void proj_mma_kernel(
    const float* __restrict__ br, float* __restrict__ out)
{
    extern __shared__ __align__(128) char ps[];
    const uint32_t sb = smem_u32(ps);
    const int tid = threadIdx.x, wid = tid >> 5, lane = tid & 31;
    const int n0 = blockIdx.x * 128, m0 = blockIdx.y * 128;
    const int wm = wid >> 1, wn = wid & 1;

    float acc[4][8][4];
    #pragma unroll
    for (int mf = 0; mf < 4; mf++)
        #pragma unroll
        for (int nf = 0; nf < 8; nf++)
            #pragma unroll
            for (int r = 0; r < 4; r++) acc[mf][nf][r] = 0.0f;

    #define ISSUE(cc, bb) do {                                                  \
        const int k0i = (cc) * 32;                                              \
        uint32_t base = sb + (bb) * PBUF_;                                      \
        _Pragma("unroll")                                                       \
        for (int q = 0; q < 4; q++) {                                           \
            int row = (tid >> 2) + q*32;                                        \
            uint32_t soff = (uint32_t)row*80 + (uint32_t)(tid & 3)*16;          \
            size_t ga = (size_t)(m0 + row)*E_ + k0i + (tid & 3)*8;              \
            size_t gb = (size_t)(n0 + row)*E_ + k0i + (tid & 3)*8;              \
            cpa16(base + 0*PTILE_ + soff, g_zh16 + ga);                         \
            cpa16(base + 1*PTILE_ + soff, g_zl16 + ga);                         \
            cpa16(base + 2*PTILE_ + soff, g_w16  + gb);                         \
        }                                                                       \
        asm volatile("cp.async.commit_group;" ::: "memory");                    \
    } while (0)

    const uint32_t koff4p = (uint32_t)((lane & 7) + ((lane >> 4) << 3))*80 + (((lane >> 3) & 1) << 4);
    const int am = lane & 15;

    ISSUE(0, 0);
    for (int c = 0; c < 32; c++) {
        const int buf = c & 1;
        if (c + 1 < 32) {
            ISSUE(c + 1, buf ^ 1);
            asm volatile("cp.async.wait_group 1;" ::: "memory");
        } else {
            asm volatile("cp.async.wait_group 0;" ::: "memory");
        }
        __syncthreads();

        const uint32_t Ah = sb + buf*PBUF_;
        const uint32_t Al = Ah + PTILE_;
        const uint32_t Bw = Ah + 2*PTILE_;

        #pragma unroll
        for (int ks = 0; ks < 2; ks++) {
            uint32_t ah[4][4], al[4][4], b4[4][4];
            const uint32_t akoff = (uint32_t)(ks*32 + (lane >> 4)*16);
            #pragma unroll
            for (int mf = 0; mf < 4; mf++) {
                uint32_t ro = (uint32_t)(wm*64 + mf*16 + am)*80 + akoff;
                ldsm4(ah[mf], Ah + ro);
                ldsm4(al[mf], Al + ro);
            }
            #pragma unroll
            for (int p = 0; p < 4; p++) {
                uint32_t ro = (uint32_t)(wn*64 + p*16)*80 + koff4p + ks*32;
                ldsm4(b4[p], Bw + ro);
            }
            // term 1: ah * b
            #pragma unroll
            for (int p = 0; p < 4; p++)
                #pragma unroll
                for (int mf = 0; mf < 4; mf++) {
                    mma_f16(acc[mf][2*p],   ah[mf], b4[p]);
                    mma_f16(acc[mf][2*p+1], ah[mf], b4[p] + 2);
                }
            // term 2: al * b
            #pragma unroll
            for (int p = 0; p < 4; p++)
                #pragma unroll
                for (int mf = 0; mf < 4; mf++) {
                    mma_f16(acc[mf][2*p],   al[mf], b4[p]);
                    mma_f16(acc[mf][2*p+1], al[mf], b4[p] + 2);
                }
        }
        __syncthreads();
    }

    const int g = lane >> 2, tg = lane & 3;
    #pragma unroll
    for (int nf = 0; nf < 8; nf++) {
        const int col = n0 + wn*64 + nf*8 + tg*2;
        float2 bb = *(const float2*)&br[col];
        #pragma unroll
        for (int mf = 0; mf < 4; mf++) {
            const int row = m0 + wm*64 + mf*16 + g;
            float2 v0 = make_float2(acc[mf][nf][0] + bb.x, acc[mf][nf][1] + bb.y);
            float2 v1 = make_float2(acc[mf][nf][2] + bb.x, acc[mf][nf][3] + bb.y);
            *(float2*)&out[(size_t)row*E_ + col]       = v0;
            *(float2*)&out[(size_t)(row + 8)*E_ + col] = v1;
        }
    }
}

// ---------------------------------------------------------------------------
extern "C" void kernel_launch(void* const* d_in, const int* in_sizes, int n_in,
                              void* d_out, int out_size)
{
    const float* x  = (const float*)d_in[0];
    const float* Wq = (const float*)d_in[1];
    const float* Wk = (const float*)d_in[2];
    const float* Wv = (const float*)d_in[3];
    const float* Er = (const float*)d_in[4];
    const float* Wr = (const float*)d_in[5];
    const float* br = (const float*)d_in[6];
    float* out = (float*)d_out;

    const int smem_qkv = 92160;
    cudaFuncSetAttribute(qkv_mma_kernel,
                         cudaFuncAttributeMaxDynamicSharedMemorySize, smem_qkv);
    qkv_mma_kernel<<<dim3(T_/128, H_, B_), 256, smem_qkv>>>(x, Wq, Wk, Wv, Er);

    wconv_kernel<<<(E_*E_)/(256*4), 256>>>(Wr);

    const int smem_attn = 92160;    // 2-stage; 2 CTAs/SM
    cudaFuncSetAttribute(attn_mma_kernel,
                         cudaFuncAttributeMaxDynamicSharedMemorySize, smem_attn);
    attn_mma_kernel<<<dim3(T_/128, BH_), 256, smem_attn>>>();

    const int smem_proj = 2 * PBUF_;  // 61440; 2 CTAs/SM
    cudaFuncSetAttribute(proj_mma_kernel,
                         cudaFuncAttributeMaxDynamicSharedMemorySize, smem_proj);
    proj_mma_kernel<<<dim3(E_/128, (B_*T_)/128), 128, smem_proj>>>(br, out);
}